// round 13
// baseline (speedup 1.0000x reference)
#include <cuda_runtime.h>
#include <cuda_fp16.h>
#include <stdint.h>
#include <math.h>

typedef unsigned int u32;

#define MD    1536
#define SHID  2048
#define SENC  256
#define TTOT  2304
#define NHEAD 24
#define HDIM  64

// ---------------- scratch (__device__ globals: allocation-free rule) --------
__device__ __half g_h16 [SHID * MD];
__device__ __half g_e16 [SENC * MD];
__device__ __half g_w16 [6 * MD * MD];
__device__ __half g_Q16 [SHID * MD];
__device__ __half g_K16 [TTOT * MD];
__device__ __half g_V16 [TTOT * MD];
__device__ __half g_AO16[SHID * MD];

// ---------------- warp-mma helpers ------------------------------------------
__device__ __forceinline__ void ldsm4(u32* r, u32 addr)
{
    asm volatile("ldmatrix.sync.aligned.m8n8.x4.shared.b16 {%0,%1,%2,%3}, [%4];"
                 : "=r"(r[0]), "=r"(r[1]), "=r"(r[2]), "=r"(r[3]) : "r"(addr));
}

__device__ __forceinline__ void ldsm4t(u32* r, u32 addr)
{
    asm volatile("ldmatrix.sync.aligned.m8n8.x4.trans.shared.b16 {%0,%1,%2,%3}, [%4];"
                 : "=r"(r[0]), "=r"(r[1]), "=r"(r[2]), "=r"(r[3]) : "r"(addr));
}

__device__ __forceinline__ void mma16816(float* c, const u32* a, u32 b0, u32 b1)
{
    asm volatile(
        "mma.sync.aligned.m16n8k16.row.col.f32.f16.f16.f32 "
        "{%0,%1,%2,%3}, {%4,%5,%6,%7}, {%8,%9}, {%0,%1,%2,%3};"
        : "+f"(c[0]), "+f"(c[1]), "+f"(c[2]), "+f"(c[3])
        : "r"(a[0]), "r"(a[1]), "r"(a[2]), "r"(a[3]), "r"(b0), "r"(b1));
}

__device__ __forceinline__ u32 packh2(float x, float y)
{
    __half2 h = __floats2half2_rn(x, y);
    return *reinterpret_cast<u32*>(&h);
}

__device__ __forceinline__ void cp16(u32 smem_dst, const void* gmem_src)
{
    asm volatile("cp.async.cg.shared.global [%0], [%1], 16;"
                 :: "r"(smem_dst), "l"(gmem_src));
}

__device__ __forceinline__ void cp_commit()
{
    asm volatile("cp.async.commit_group;");
}

__device__ __forceinline__ void cp_wait1()
{
    asm volatile("cp.async.wait_group 1;");
}

__device__ __forceinline__ void cp_wait0()
{
    asm volatile("cp.async.wait_group 0;");
}

// ---------------- merged fp32 -> fp16 convert (one launch, 8 segments) -----
struct CvtJobs
{
    const float* src[8];
    __half*      dst[8];
    int          n4[8];
};

__global__ __launch_bounds__(256) void cvt_multi(CvtJobs jobs)
{
    int seg = blockIdx.y;
    const float* __restrict__ src = jobs.src[seg];
    __half* __restrict__ dst = jobs.dst[seg];
    int n4 = jobs.n4[seg];
    int i0 = (blockIdx.x * 256 + threadIdx.x) * 4;
    if (i0 >= n4) return;
    #pragma unroll
    for (int j = 0; j < 4; j++)
    {
        int i = i0 + j;
        float4 v = ((const float4*)src)[i];
        ((__half2*)dst)[2 * i + 0] = __floats2half2_rn(v.x, v.y);
        ((__half2*)dst)[2 * i + 1] = __floats2half2_rn(v.z, v.w);
    }
}

// ---------------- multi-job fp16 GEMM, small CTAs for co-residency ----------
// C[z] = f( A[z][M,K] @ W[z][N,K]^T + bias[z] )
// mode 0: f32 out, 1: f16 out, 2: f16 out with per-64-col-head RMSNorm*scale.
// BM=128, BN=64, BK=32, 64 threads (2 warps stacked on M), warp tile 64x64.
// 3-stage cp.async pipeline. Small CTA -> 4 CTAs/SM resident (8 warps/SM),
// hiding ldsm/barrier latency via cross-CTA interleave.
struct GemmJobs
{
    const __half* A[5];
    const __half* W[5];
    const float*  bias[5];
    const float*  normw[5];
    void*         C[5];
    int           M[5];
    int           mode[5];
    float         scale[5];
};

#define GSTG_A   10240            // A stage: 128 rows * 40 halves
#define GSTG_BB  5120             // B stage: 64 rows * 40 halves
#define GB_OFF   30720            // 3 A stages
#define G_SMEM   46080

__global__ __launch_bounds__(64) void gemm_f16x(GemmJobs job, int N, int K)
{
    extern __shared__ __align__(16) char gsm[];
    const int z = blockIdx.z;
    const int bm = blockIdx.y * 128;
    if (bm >= job.M[z]) return;
    const __half* __restrict__ A = job.A[z];
    const __half* __restrict__ W = job.W[z];
    const float* __restrict__ bias = job.bias[z];
    const float* __restrict__ normw = job.normw[z];
    void* Cout = job.C[z];
    const int mode = job.mode[z];
    const float nscale = job.scale[z];

    const int bn = blockIdx.x * 64;
    const int tid  = threadIdx.x;
    const int lane = tid & 31;
    const int warp = tid >> 5;      // 0..1, stacked on M
    const int oct = lane >> 3;
    const int oj  = lane & 7;

    const u32 sA = (u32)__cvta_generic_to_shared(gsm);
    const u32 sB = sA + GB_OFF;

    float acc[4][8][4];
    #pragma unroll
    for (int mi = 0; mi < 4; mi++)
        #pragma unroll
        for (int ni = 0; ni < 8; ni++)
            #pragma unroll
            for (int x = 0; x < 4; x++) acc[mi][ni][x] = 0.0f;

    const int KT = K >> 5;

    // prologue: tiles 0, 1.  A: 512 chunks (8/thread); B: 256 chunks (4/thread)
    #pragma unroll
    for (int pt = 0; pt < 2; pt++)
    {
        const u32 soA = (u32)pt * GSTG_A;
        const u32 soB = (u32)pt * GSTG_BB;
        #pragma unroll
        for (int l = 0; l < 8; l++)
        {
            int idx = tid + l * 64;
            int row = idx >> 2;
            int ch  = idx & 3;
            cp16(sA + soA + (u32)(row * 40 + ch * 8) * 2u,
                 A + (size_t)(bm + row) * K + pt * 32 + ch * 8);
        }
        #pragma unroll
        for (int l = 0; l < 4; l++)
        {
            int idx = tid + l * 64;
            int row = idx >> 2;
            int ch  = idx & 3;
            cp16(sB + soB + (u32)(row * 40 + ch * 8) * 2u,
                 W + (size_t)(bn + row) * K + pt * 32 + ch * 8);
        }
        cp_commit();
    }

    for (int kt = 0; kt < KT; kt++)
    {
        if (kt == KT - 1) cp_wait0(); else cp_wait1();
        __syncthreads();

        if (kt + 2 < KT)
        {
            const int nt = kt + 2;
            const u32 soA = (u32)(nt % 3) * GSTG_A;
            const u32 soB = (u32)(nt % 3) * GSTG_BB;
            #pragma unroll
            for (int l = 0; l < 8; l++)
            {
                int idx = tid + l * 64;
                int row = idx >> 2;
                int ch  = idx & 3;
                cp16(sA + soA + (u32)(row * 40 + ch * 8) * 2u,
                     A + (size_t)(bm + row) * K + nt * 32 + ch * 8);
            }
            #pragma unroll
            for (int l = 0; l < 4; l++)
            {
                int idx = tid + l * 64;
                int row = idx >> 2;
                int ch  = idx & 3;
                cp16(sB + soB + (u32)(row * 40 + ch * 8) * 2u,
                     W + (size_t)(bn + row) * K + nt * 32 + ch * 8);
            }
            cp_commit();
        }

        const u32 soA = (u32)(kt % 3) * GSTG_A;
        const u32 soB = (u32)(kt % 3) * GSTG_BB;
        #pragma unroll
        for (int ks = 0; ks < 2; ks++)
        {
            const int ksh = ks * 16;
            u32 af[4][4];
            #pragma unroll
            for (int mi = 0; mi < 4; mi++)
            {
                int row = warp * 64 + mi * 16 + (oct & 1) * 8 + oj;
                int col = ksh + (oct >> 1) * 8;
                ldsm4(af[mi], sA + soA + (u32)(row * 40 + col) * 2u);
            }
            u32 bf[4][4];
            #pragma unroll
            for (int nb = 0; nb < 4; nb++)
            {
                int row = nb * 16 + (oct >> 1) * 8 + oj;
                int col = ksh + (oct & 1) * 8;
                ldsm4(bf[nb], sB + soB + (u32)(row * 40 + col) * 2u);
            }
            #pragma unroll
            for (int mi = 0; mi < 4; mi++)
            {
                #pragma unroll
                for (int nb = 0; nb < 4; nb++)
                {
                    mma16816(acc[mi][2 * nb + 0], af[mi], bf[nb][0], bf[nb][1]);
                    mma16816(acc[mi][2 * nb + 1], af[mi], bf[nb][2], bf[nb][3]);
                }
            }
        }
    }

    // ---- epilogue (warp-local) ----
    #pragma unroll
    for (int ni = 0; ni < 8; ni++)
    {
        int col = bn + ni * 8 + (lane & 3) * 2;
        float b0 = bias[col];
        float b1 = bias[col + 1];
        #pragma unroll
        for (int mi = 0; mi < 4; mi++)
        {
            acc[mi][ni][0] += b0;
            acc[mi][ni][1] += b1;
            acc[mi][ni][2] += b0;
            acc[mi][ni][3] += b1;
        }
    }

    if (mode == 2)
    {
        // fused per-head RMSNorm: head = this block's 64 cols (warp-local sums)
        __half* C = (__half*)Cout;
        #pragma unroll
        for (int mi = 0; mi < 4; mi++)
        {
            float s0 = 0.0f;
            float s1 = 0.0f;
            #pragma unroll
            for (int ni = 0; ni < 8; ni++)
            {
                s0 += acc[mi][ni][0] * acc[mi][ni][0] + acc[mi][ni][1] * acc[mi][ni][1];
                s1 += acc[mi][ni][2] * acc[mi][ni][2] + acc[mi][ni][3] * acc[mi][ni][3];
            }
            s0 += __shfl_xor_sync(0xffffffffu, s0, 1);
            s0 += __shfl_xor_sync(0xffffffffu, s0, 2);
            s1 += __shfl_xor_sync(0xffffffffu, s1, 1);
            s1 += __shfl_xor_sync(0xffffffffu, s1, 2);
            float rs0 = rsqrtf(s0 * (1.0f / HDIM) + 1e-6f) * nscale;
            float rs1 = rsqrtf(s1 * (1.0f / HDIM) + 1e-6f) * nscale;
            int row = bm + warp * 64 + mi * 16 + (lane >> 2);
            #pragma unroll
            for (int ni = 0; ni < 8; ni++)
            {
                int wcol = ni * 8 + (lane & 3) * 2;
                float w0 = normw[wcol];
                float w1 = normw[wcol + 1];
                int col = bn + wcol;
                *(__half2*)(C + (size_t)row * N + col) =
                    __floats2half2_rn(acc[mi][ni][0] * rs0 * w0, acc[mi][ni][1] * rs0 * w1);
                *(__half2*)(C + (size_t)(row + 8) * N + col) =
                    __floats2half2_rn(acc[mi][ni][2] * rs1 * w0, acc[mi][ni][3] * rs1 * w1);
            }
        }
    }
    else if (mode == 1)
    {
        __half* C = (__half*)Cout;
        #pragma unroll
        for (int mi = 0; mi < 4; mi++)
        {
            int row = bm + warp * 64 + mi * 16 + (lane >> 2);
            #pragma unroll
            for (int ni = 0; ni < 8; ni++)
            {
                int col = bn + ni * 8 + (lane & 3) * 2;
                *(__half2*)(C + (size_t)row * N + col) =
                    __floats2half2_rn(acc[mi][ni][0], acc[mi][ni][1]);
                *(__half2*)(C + (size_t)(row + 8) * N + col) =
                    __floats2half2_rn(acc[mi][ni][2], acc[mi][ni][3]);
            }
        }
    }
    else
    {
        float* C = (float*)Cout;
        #pragma unroll
        for (int mi = 0; mi < 4; mi++)
        {
            int row = bm + warp * 64 + mi * 16 + (lane >> 2);
            #pragma unroll
            for (int ni = 0; ni < 8; ni++)
            {
                int col = bn + ni * 8 + (lane & 3) * 2;
                *(float2*)(C + (size_t)row * N + col) =
                    make_float2(acc[mi][ni][0], acc[mi][ni][1]);
                *(float2*)(C + (size_t)(row + 8) * N + col) =
                    make_float2(acc[mi][ni][2], acc[mi][ni][3]);
            }
        }
    }
}

// ---------------- fp16 flash attention (tensor core, cp.async K/V) ----------
#define FQ_OFF   0
#define FK_OFF   18432
#define FV_OFF   36864
#define FM_OFF   55296
#define F_SMEM   64512
#define KV_STAGE 9216

__global__ __launch_bounds__(256) void flash16(
    const __half* __restrict__ Qg, const __half* __restrict__ Kg,
    const __half* __restrict__ Vg, const float* __restrict__ mask,
    __half* __restrict__ AO)
{
    extern __shared__ __align__(16) char fsm[];
    __half* Qs = (__half*)(fsm + FQ_OFF);
    float* smask = (float*)(fsm + FM_OFF);

    const int h  = blockIdx.y;
    const int bq = blockIdx.x * 128;
    const int tid  = threadIdx.x;
    const int lane = tid & 31;
    const int warp = tid >> 5;
    const int oct = lane >> 3;
    const int oj  = lane & 7;
    const int cb  = (lane & 3) * 2;

    const u32 smemBase = (u32)__cvta_generic_to_shared(fsm);
    const u32 sQ = smemBase + FQ_OFF;
    const u32 sK = smemBase + FK_OFF;
    const u32 sV = smemBase + FV_OFF;

    #pragma unroll
    for (int l = 0; l < 4; l++)
    {
        int idx = tid + l * 256;
        int r  = idx >> 3;
        int cc = (idx & 7) * 8;
        *(int4*)(Qs + r * 72 + cc) =
            *(const int4*)(Qg + (size_t)(bq + r) * MD + h * HDIM + cc);
    }
    for (int i = tid; i < TTOT; i += 256) smask[i] = mask[i];

    {
        #pragma unroll
        for (int l = 0; l < 2; l++)
        {
            int idx = tid + l * 256;
            int r  = idx >> 3;
            int cc = (idx & 7) * 8;
            cp16(sK + (u32)(r * 72 + cc) * 2u, Kg + (size_t)r * MD + h * HDIM + cc);
            cp16(sV + (u32)(r * 72 + cc) * 2u, Vg + (size_t)r * MD + h * HDIM + cc);
        }
        cp_commit();
    }

    __syncthreads();
    u32 qa[4][4];
    #pragma unroll
    for (int kf = 0; kf < 4; kf++)
    {
        int row = warp * 16 + (oct & 1) * 8 + oj;
        int col = kf * 16 + (oct >> 1) * 8;
        ldsm4(qa[kf], sQ + (u32)(row * 72 + col) * 2u);
    }

    float m0 = -1e30f;
    float m1 = -1e30f;
    float l0 = 0.0f;
    float l1 = 0.0f;
    float oacc[8][4];
    #pragma unroll
    for (int dt = 0; dt < 8; dt++)
    {
        #pragma unroll
        for (int x = 0; x < 4; x++) oacc[dt][x] = 0.0f;
    }

    const int NT = TTOT / 64;
    for (int t = 0; t < NT; t++)
    {
        if (t + 1 < NT)
        {
            const u32 so = (u32)((t + 1) & 1) * KV_STAGE;
            #pragma unroll
            for (int l = 0; l < 2; l++)
            {
                int idx = tid + l * 256;
                int r  = idx >> 3;
                int cc = (idx & 7) * 8;
                cp16(sK + so + (u32)(r * 72 + cc) * 2u,
                     Kg + (size_t)((t + 1) * 64 + r) * MD + h * HDIM + cc);
                cp16(sV + so + (u32)(r * 72 + cc) * 2u,
                     Vg + (size_t)((t + 1) * 64 + r) * MD + h * HDIM + cc);
            }
            cp_commit();
            cp_wait1();
        }
        else
        {
            cp_wait0();
        }
        __syncthreads();

        const u32 so = (u32)(t & 1) * KV_STAGE;

        float s[8][4];
        #pragma unroll
        for (int jt = 0; jt < 8; jt++)
        {
            #pragma unroll
            for (int x = 0; x < 4; x++) s[jt][x] = 0.0f;
        }
        #pragma unroll
        for (int nb = 0; nb < 4; nb++)
        {
            #pragma unroll
            for (int kf = 0; kf < 4; kf++)
            {
                u32 bfr[4];
                int row = nb * 16 + (oct >> 1) * 8 + oj;
                int col = kf * 16 + (oct & 1) * 8;
                ldsm4(bfr, sK + so + (u32)(row * 72 + col) * 2u);
                mma16816(s[2 * nb + 0], qa[kf], bfr[0], bfr[1]);
                mma16816(s[2 * nb + 1], qa[kf], bfr[2], bfr[3]);
            }
        }

        float mx0 = -1e30f;
        float mx1 = -1e30f;
        #pragma unroll
        for (int jt = 0; jt < 8; jt++)
        {
            float mk0 = smask[t * 64 + jt * 8 + cb];
            float mk1 = smask[t * 64 + jt * 8 + cb + 1];
            s[jt][0] += mk0;
            s[jt][1] += mk1;
            s[jt][2] += mk0;
            s[jt][3] += mk1;
            mx0 = fmaxf(mx0, fmaxf(s[jt][0], s[jt][1]));
            mx1 = fmaxf(mx1, fmaxf(s[jt][2], s[jt][3]));
        }
        mx0 = fmaxf(mx0, __shfl_xor_sync(0xffffffffu, mx0, 1));
        mx0 = fmaxf(mx0, __shfl_xor_sync(0xffffffffu, mx0, 2));
        mx1 = fmaxf(mx1, __shfl_xor_sync(0xffffffffu, mx1, 1));
        mx1 = fmaxf(mx1, __shfl_xor_sync(0xffffffffu, mx1, 2));
        float mn0 = fmaxf(m0, mx0);
        float a0  = __expf(m0 - mn0);
        m0 = mn0;
        float mn1 = fmaxf(m1, mx1);
        float a1  = __expf(m1 - mn1);
        m1 = mn1;

        float rs0 = 0.0f;
        float rs1 = 0.0f;
        #pragma unroll
        for (int jt = 0; jt < 8; jt++)
        {
            s[jt][0] = __expf(s[jt][0] - m0); rs0 += s[jt][0];
            s[jt][1] = __expf(s[jt][1] - m0); rs0 += s[jt][1];
            s[jt][2] = __expf(s[jt][2] - m1); rs1 += s[jt][2];
            s[jt][3] = __expf(s[jt][3] - m1); rs1 += s[jt][3];
        }
        l0 = l0 * a0 + rs0;
        l1 = l1 * a1 + rs1;

        u32 pa[4][4];
        #pragma unroll
        for (int kf = 0; kf < 4; kf++)
        {
            pa[kf][0] = packh2(s[2 * kf + 0][0], s[2 * kf + 0][1]);
            pa[kf][1] = packh2(s[2 * kf + 0][2], s[2 * kf + 0][3]);
            pa[kf][2] = packh2(s[2 * kf + 1][0], s[2 * kf + 1][1]);
            pa[kf][3] = packh2(s[2 * kf + 1][2], s[2 * kf + 1][3]);
        }
        #pragma unroll
        for (int dt = 0; dt < 8; dt++)
        {
            oacc[dt][0] *= a0;
            oacc[dt][1] *= a0;
            oacc[dt][2] *= a1;
            oacc[dt][3] *= a1;
        }
        #pragma unroll
        for (int db = 0; db < 4; db++)
        {
            #pragma unroll
            for (int kf = 0; kf < 4; kf++)
            {
                u32 bfr[4];
                int row = kf * 16 + (oct & 1) * 8 + oj;
                int col = db * 16 + (oct >> 1) * 8;
                ldsm4t(bfr, sV + so + (u32)(row * 72 + col) * 2u);
                mma16816(oacc[2 * db + 0], pa[kf], bfr[0], bfr[1]);
                mma16816(oacc[2 * db + 1], pa[kf], bfr[2], bfr[3]);
            }
        }
        __syncthreads();
    }

    l0 += __shfl_xor_sync(0xffffffffu, l0, 1);
    l0 += __shfl_xor_sync(0xffffffffu, l0, 2);
    l1 += __shfl_xor_sync(0xffffffffu, l1, 1);
    l1 += __shfl_xor_sync(0xffffffffu, l1, 2);
    float inv0 = 1.0f / l0;
    float inv1 = 1.0f / l1;

    #pragma unroll
    for (int dt = 0; dt < 8; dt++)
    {
        int row = bq + warp * 16 + (lane >> 2);
        int col = h * HDIM + dt * 8 + cb;
        *(__half2*)(AO + (size_t)row * MD + col) =
            __floats2half2_rn(oacc[dt][0] * inv0, oacc[dt][1] * inv0);
        *(__half2*)(AO + (size_t)(row + 8) * MD + col) =
            __floats2half2_rn(oacc[dt][2] * inv1, oacc[dt][3] * inv1);
    }
}

// ----------------------------------------------------------------------------
extern "C" void kernel_launch(void* const* d_in, const int* in_sizes, int n_in,
                              void* d_out, int out_size)
{
    const float* hidden = (const float*)d_in[0];
    const float* enc    = (const float*)d_in[1];
    const float* mask   = (const float*)d_in[2];
    const float* qw  = (const float*)d_in[3];
    const float* qb  = (const float*)d_in[4];
    const float* kw  = (const float*)d_in[5];
    const float* kb  = (const float*)d_in[6];
    const float* vw  = (const float*)d_in[7];
    const float* vb  = (const float*)d_in[8];
    const float* nq  = (const float*)d_in[9];
    const float* nk  = (const float*)d_in[10];
    const float* akw = (const float*)d_in[13];
    const float* akb = (const float*)d_in[14];
    const float* avw = (const float*)d_in[15];
    const float* avb = (const float*)d_in[16];
    const float* nak = (const float*)d_in[18];
    const float* ow  = (const float*)d_in[19];
    const float* ob  = (const float*)d_in[20];
    float* outp = (float*)d_out;

    __half* h16 = 0;
    __half* e16 = 0;
    __half* w16 = 0;
    __half* Q16 = 0;
    __half* K16 = 0;
    __half* V16 = 0;
    __half* AO16 = 0;
    cudaGetSymbolAddress((void**)&h16,  g_h16);
    cudaGetSymbolAddress((void**)&e16,  g_e16);
    cudaGetSymbolAddress((void**)&w16,  g_w16);
    cudaGetSymbolAddress((void**)&Q16,  g_Q16);
    cudaGetSymbolAddress((void**)&K16,  g_K16);
    cudaGetSymbolAddress((void**)&V16,  g_V16);
    cudaGetSymbolAddress((void**)&AO16, g_AO16);

    __half* wq16  = w16 + 0 * (size_t)MD * MD;
    __half* wk16  = w16 + 1 * (size_t)MD * MD;
    __half* wv16  = w16 + 2 * (size_t)MD * MD;
    __half* wak16 = w16 + 3 * (size_t)MD * MD;
    __half* wav16 = w16 + 4 * (size_t)MD * MD;
    __half* wo16  = w16 + 5 * (size_t)MD * MD;

    const int nw4 = MD * MD / 4;
    const int nh4 = SHID * MD / 4;
    const int ne4 = SENC * MD / 4;

    CvtJobs jobs;
    jobs.src[0] = hidden;  jobs.dst[0] = h16;   jobs.n4[0] = nh4;
    jobs.src[1] = enc;     jobs.dst[1] = e16;   jobs.n4[1] = ne4;
    jobs.src[2] = qw;      jobs.dst[2] = wq16;  jobs.n4[2] = nw4;
    jobs.src[3] = kw;      jobs.dst[3] = wk16;  jobs.n4[3] = nw4;
    jobs.src[4] = vw;      jobs.dst[4] = wv16;  jobs.n4[4] = nw4;
    jobs.src[5] = akw;     jobs.dst[5] = wak16; jobs.n4[5] = nw4;
    jobs.src[6] = avw;     jobs.dst[6] = wav16; jobs.n4[6] = nw4;
    jobs.src[7] = ow;      jobs.dst[7] = wo16;  jobs.n4[7] = nw4;

    int maxB = (nh4 / 4 + 255) / 256;
    dim3 cgrid(maxB, 8, 1);
    dim3 cblk(256, 1, 1);
    cvt_multi<<<cgrid, cblk>>>(jobs);

    cudaFuncSetAttribute(gemm_f16x, cudaFuncAttributeMaxDynamicSharedMemorySize, G_SMEM);
    cudaFuncSetAttribute(flash16, cudaFuncAttributeMaxDynamicSharedMemorySize, F_SMEM);

    dim3 blk64(64, 1, 1);

    // one launch: all 5 projections (Q,K,V hidden + K,V encoder),
    // RMSNorm fused into Q and K epilogues (Q also gets 1/sqrt(64)).
    GemmJobs jP;
    jP.A[0] = h16;  jP.W[0] = wq16;  jP.bias[0] = qb;  jP.normw[0] = nq;
    jP.C[0] = Q16;  jP.M[0] = SHID;  jP.mode[0] = 2;   jP.scale[0] = 0.125f;
    jP.A[1] = h16;  jP.W[1] = wk16;  jP.bias[1] = kb;  jP.normw[1] = nk;
    jP.C[1] = K16;  jP.M[1] = SHID;  jP.mode[1] = 2;   jP.scale[1] = 1.0f;
    jP.A[2] = h16;  jP.W[2] = wv16;  jP.bias[2] = vb;  jP.normw[2] = nq;
    jP.C[2] = V16;  jP.M[2] = SHID;  jP.mode[2] = 1;   jP.scale[2] = 1.0f;
    jP.A[3] = e16;  jP.W[3] = wak16; jP.bias[3] = akb; jP.normw[3] = nak;
    jP.C[3] = K16 + (size_t)SHID * MD;  jP.M[3] = SENC;  jP.mode[3] = 2;  jP.scale[3] = 1.0f;
    jP.A[4] = e16;  jP.W[4] = wav16; jP.bias[4] = avb; jP.normw[4] = nq;
    jP.C[4] = V16 + (size_t)SHID * MD;  jP.M[4] = SENC;  jP.mode[4] = 1;  jP.scale[4] = 1.0f;
    dim3 gP(MD / 64, SHID / 128, 5);
    gemm_f16x<<<gP, blk64, G_SMEM>>>(jP, MD, MD);

    // flash attention (HMMA, cp.async double-buffered K/V)
    dim3 gF(SHID / 128, NHEAD, 1);
    dim3 fblk(256, 1, 1);
    flash16<<<gF, fblk, F_SMEM>>>(Q16, K16, V16, mask, AO16);

    // output projection -> fp32 d_out
    GemmJobs jO;
    jO.A[0] = AO16;  jO.W[0] = wo16;  jO.bias[0] = ob;  jO.normw[0] = nq;
    jO.C[0] = outp;  jO.M[0] = SHID;  jO.mode[0] = 0;   jO.scale[0] = 1.0f;
    #pragma unroll
    for (int i = 1; i < 5; i++)
    {
        jO.A[i] = AO16;  jO.W[i] = wo16;  jO.bias[i] = ob;  jO.normw[i] = nq;
        jO.C[i] = outp;  jO.M[i] = 0;     jO.mode[i] = 0;   jO.scale[i] = 1.0f;
    }
    dim3 gO(MD / 64, SHID / 128, 1);
    gemm_f16x<<<gO, blk64, G_SMEM>>>(jO, MD, MD);
}

// round 14
// speedup vs baseline: 1.7394x; 1.7394x over previous
#include <cuda_runtime.h>
#include <cuda_fp16.h>
#include <stdint.h>
#include <math.h>

typedef unsigned int u32;

#define MD    1536
#define SHID  2048
#define SENC  256
#define TTOT  2304
#define NHEAD 24
#define HDIM  64

#define LOG2E 1.44269504088896340736f

// ---------------- scratch (__device__ globals: allocation-free rule) --------
__device__ __half g_h16 [SHID * MD];
__device__ __half g_e16 [SENC * MD];
__device__ __half g_w16 [6 * MD * MD];
__device__ __half g_Q16 [SHID * MD];
__device__ __half g_K16 [TTOT * MD];
__device__ __half g_V16 [TTOT * MD];
__device__ __half g_AO16[SHID * MD];

// ---------------- warp-mma helpers ------------------------------------------
__device__ __forceinline__ void ldsm4(u32* r, u32 addr)
{
    asm volatile("ldmatrix.sync.aligned.m8n8.x4.shared.b16 {%0,%1,%2,%3}, [%4];"
                 : "=r"(r[0]), "=r"(r[1]), "=r"(r[2]), "=r"(r[3]) : "r"(addr));
}

__device__ __forceinline__ void ldsm4t(u32* r, u32 addr)
{
    asm volatile("ldmatrix.sync.aligned.m8n8.x4.trans.shared.b16 {%0,%1,%2,%3}, [%4];"
                 : "=r"(r[0]), "=r"(r[1]), "=r"(r[2]), "=r"(r[3]) : "r"(addr));
}

__device__ __forceinline__ void mma16816(float* c, const u32* a, u32 b0, u32 b1)
{
    asm volatile(
        "mma.sync.aligned.m16n8k16.row.col.f32.f16.f16.f32 "
        "{%0,%1,%2,%3}, {%4,%5,%6,%7}, {%8,%9}, {%0,%1,%2,%3};"
        : "+f"(c[0]), "+f"(c[1]), "+f"(c[2]), "+f"(c[3])
        : "r"(a[0]), "r"(a[1]), "r"(a[2]), "r"(a[3]), "r"(b0), "r"(b1));
}

__device__ __forceinline__ u32 packh2(float x, float y)
{
    __half2 h = __floats2half2_rn(x, y);
    return *reinterpret_cast<u32*>(&h);
}

__device__ __forceinline__ void cp16(u32 smem_dst, const void* gmem_src)
{
    asm volatile("cp.async.cg.shared.global [%0], [%1], 16;"
                 :: "r"(smem_dst), "l"(gmem_src));
}

__device__ __forceinline__ void cp_commit()
{
    asm volatile("cp.async.commit_group;");
}

__device__ __forceinline__ void cp_wait1()
{
    asm volatile("cp.async.wait_group 1;");
}

__device__ __forceinline__ void cp_wait0()
{
    asm volatile("cp.async.wait_group 0;");
}

// ---------------- merged fp32 -> fp16 convert (one launch, 8 segments) -----
struct CvtJobs
{
    const float* src[8];
    __half*      dst[8];
    int          n4[8];
};

__global__ __launch_bounds__(256) void cvt_multi(CvtJobs jobs)
{
    int seg = blockIdx.y;
    const float* __restrict__ src = jobs.src[seg];
    __half* __restrict__ dst = jobs.dst[seg];
    int n4 = jobs.n4[seg];
    int i0 = (blockIdx.x * 256 + threadIdx.x) * 4;
    if (i0 >= n4) return;
    #pragma unroll
    for (int j = 0; j < 4; j++)
    {
        int i = i0 + j;
        float4 v = ((const float4*)src)[i];
        ((__half2*)dst)[2 * i + 0] = __floats2half2_rn(v.x, v.y);
        ((__half2*)dst)[2 * i + 1] = __floats2half2_rn(v.z, v.w);
    }
}

// ---------------- multi-job fp16 GEMM, 64x64 warp tiles, BK=32 --------------
// (R10 configuration — best measured; do not touch)
// C[z] = f( A[z][M,K] @ W[z][N,K]^T + bias[z] )
// mode 0: f32 out, 1: f16 out, 2: f16 out with per-64-col-head RMSNorm*scale.
// BM=128, BN=128, BK=32, 128 threads (4 warps: 2m x 2n), warp tile 64x64.
struct GemmJobs
{
    const __half* A[5];
    const __half* W[5];
    const float*  bias[5];
    const float*  normw[5];
    void*         C[5];
    int           M[5];
    int           mode[5];
    float         scale[5];
};

#define GSTG_B   10240            // one stage of one matrix: 128*40 halves
#define GB_OFF   30720            // 3 stages of A
#define G_SMEM   61440

__global__ __launch_bounds__(128) void gemm_f16x(GemmJobs job, int N, int K)
{
    extern __shared__ __align__(16) char gsm[];
    const int z = blockIdx.z;
    const int bm = blockIdx.y * 128;
    if (bm >= job.M[z]) return;
    const __half* __restrict__ A = job.A[z];
    const __half* __restrict__ W = job.W[z];
    const float* __restrict__ bias = job.bias[z];
    const float* __restrict__ normw = job.normw[z];
    void* Cout = job.C[z];
    const int mode = job.mode[z];
    const float nscale = job.scale[z];

    const int bn = blockIdx.x * 128;
    const int tid  = threadIdx.x;
    const int lane = tid & 31;
    const int warp = tid >> 5;      // 0..3
    const int wm  = warp & 1;       // 2 warp-rows of 64
    const int wn  = warp >> 1;      // 2 warp-cols of 64
    const int oct = lane >> 3;
    const int oj  = lane & 7;

    const u32 sA = (u32)__cvta_generic_to_shared(gsm);
    const u32 sB = sA + GB_OFF;

    float acc[4][8][4];
    #pragma unroll
    for (int mi = 0; mi < 4; mi++)
        #pragma unroll
        for (int ni = 0; ni < 8; ni++)
            #pragma unroll
            for (int x = 0; x < 4; x++) acc[mi][ni][x] = 0.0f;

    const int KT = K >> 5;

    // prologue: tiles 0, 1
    #pragma unroll
    for (int pt = 0; pt < 2; pt++)
    {
        const u32 so = (u32)pt * GSTG_B;
        #pragma unroll
        for (int l = 0; l < 4; l++)
        {
            int idx = tid + l * 128;
            int row = idx >> 2;
            int ch  = idx & 3;
            u32 d = so + (u32)(row * 40 + ch * 8) * 2u;
            cp16(sA + d, A + (size_t)(bm + row) * K + pt * 32 + ch * 8);
            cp16(sB + d, W + (size_t)(bn + row) * K + pt * 32 + ch * 8);
        }
        cp_commit();
    }

    for (int kt = 0; kt < KT; kt++)
    {
        if (kt == KT - 1) cp_wait0(); else cp_wait1();
        __syncthreads();

        if (kt + 2 < KT)
        {
            const int nt = kt + 2;
            const u32 so = (u32)(nt % 3) * GSTG_B;
            #pragma unroll
            for (int l = 0; l < 4; l++)
            {
                int idx = tid + l * 128;
                int row = idx >> 2;
                int ch  = idx & 3;
                u32 d = so + (u32)(row * 40 + ch * 8) * 2u;
                cp16(sA + d, A + (size_t)(bm + row) * K + nt * 32 + ch * 8);
                cp16(sB + d, W + (size_t)(bn + row) * K + nt * 32 + ch * 8);
            }
            cp_commit();
        }

        const u32 so = (u32)(kt % 3) * GSTG_B;
        #pragma unroll
        for (int ks = 0; ks < 2; ks++)
        {
            const int ksh = ks * 16;
            u32 af[4][4];
            #pragma unroll
            for (int mi = 0; mi < 4; mi++)
            {
                int row = wm * 64 + mi * 16 + (oct & 1) * 8 + oj;
                int col = ksh + (oct >> 1) * 8;
                ldsm4(af[mi], sA + so + (u32)(row * 40 + col) * 2u);
            }
            u32 bf[4][4];
            #pragma unroll
            for (int nb = 0; nb < 4; nb++)
            {
                int row = wn * 64 + nb * 16 + (oct >> 1) * 8 + oj;
                int col = ksh + (oct & 1) * 8;
                ldsm4(bf[nb], sB + so + (u32)(row * 40 + col) * 2u);
            }
            #pragma unroll
            for (int mi = 0; mi < 4; mi++)
            {
                #pragma unroll
                for (int nb = 0; nb < 4; nb++)
                {
                    mma16816(acc[mi][2 * nb + 0], af[mi], bf[nb][0], bf[nb][1]);
                    mma16816(acc[mi][2 * nb + 1], af[mi], bf[nb][2], bf[nb][3]);
                }
            }
        }
    }

    // ---- epilogue ----
    #pragma unroll
    for (int ni = 0; ni < 8; ni++)
    {
        int col = bn + wn * 64 + ni * 8 + (lane & 3) * 2;
        float b0 = bias[col];
        float b1 = bias[col + 1];
        #pragma unroll
        for (int mi = 0; mi < 4; mi++)
        {
            acc[mi][ni][0] += b0;
            acc[mi][ni][1] += b1;
            acc[mi][ni][2] += b0;
            acc[mi][ni][3] += b1;
        }
    }

    if (mode == 2)
    {
        __half* C = (__half*)Cout;
        #pragma unroll
        for (int mi = 0; mi < 4; mi++)
        {
            float s0 = 0.0f;
            float s1 = 0.0f;
            #pragma unroll
            for (int ni = 0; ni < 8; ni++)
            {
                s0 += acc[mi][ni][0] * acc[mi][ni][0] + acc[mi][ni][1] * acc[mi][ni][1];
                s1 += acc[mi][ni][2] * acc[mi][ni][2] + acc[mi][ni][3] * acc[mi][ni][3];
            }
            s0 += __shfl_xor_sync(0xffffffffu, s0, 1);
            s0 += __shfl_xor_sync(0xffffffffu, s0, 2);
            s1 += __shfl_xor_sync(0xffffffffu, s1, 1);
            s1 += __shfl_xor_sync(0xffffffffu, s1, 2);
            float rs0 = rsqrtf(s0 * (1.0f / HDIM) + 1e-6f) * nscale;
            float rs1 = rsqrtf(s1 * (1.0f / HDIM) + 1e-6f) * nscale;
            int row = bm + wm * 64 + mi * 16 + (lane >> 2);
            #pragma unroll
            for (int ni = 0; ni < 8; ni++)
            {
                int wcol = ni * 8 + (lane & 3) * 2;
                float w0 = normw[wcol];
                float w1 = normw[wcol + 1];
                int col = bn + wn * 64 + wcol;
                *(__half2*)(C + (size_t)row * N + col) =
                    __floats2half2_rn(acc[mi][ni][0] * rs0 * w0, acc[mi][ni][1] * rs0 * w1);
                *(__half2*)(C + (size_t)(row + 8) * N + col) =
                    __floats2half2_rn(acc[mi][ni][2] * rs1 * w0, acc[mi][ni][3] * rs1 * w1);
            }
        }
    }
    else if (mode == 1)
    {
        __half* C = (__half*)Cout;
        #pragma unroll
        for (int mi = 0; mi < 4; mi++)
        {
            int row = bm + wm * 64 + mi * 16 + (lane >> 2);
            #pragma unroll
            for (int ni = 0; ni < 8; ni++)
            {
                int col = bn + wn * 64 + ni * 8 + (lane & 3) * 2;
                *(__half2*)(C + (size_t)row * N + col) =
                    __floats2half2_rn(acc[mi][ni][0], acc[mi][ni][1]);
                *(__half2*)(C + (size_t)(row + 8) * N + col) =
                    __floats2half2_rn(acc[mi][ni][2], acc[mi][ni][3]);
            }
        }
    }
    else
    {
        float* C = (float*)Cout;
        #pragma unroll
        for (int mi = 0; mi < 4; mi++)
        {
            int row = bm + wm * 64 + mi * 16 + (lane >> 2);
            #pragma unroll
            for (int ni = 0; ni < 8; ni++)
            {
                int col = bn + wn * 64 + ni * 8 + (lane & 3) * 2;
                *(float2*)(C + (size_t)row * N + col) =
                    make_float2(acc[mi][ni][0], acc[mi][ni][1]);
                *(float2*)(C + (size_t)(row + 8) * N + col) =
                    make_float2(acc[mi][ni][2], acc[mi][ni][3]);
            }
        }
    }
}

// ---------------- fp16 flash attention (3-stage KV ring, exp2 softmax) ------
// 256 threads = 8 warps; q-tile 128 (16 rows/warp), kv-tile 64, d=64.
// Q pre-scaled by log2(e)/sqrt(HDIM); mask pre-scaled by log2(e) on load.
// 3 KV stages -> single __syncthreads per kv-tile (the mid-body barrier at
// iter t-1 already orders readers of the stage overwritten at iter t).
#define FQ_OFF   0
#define FK_OFF   18432
#define FV_OFF   46080
#define FM_OFF   73728
#define F_SMEM   82944
#define KV_STAGE 9216

__global__ __launch_bounds__(256) void flash16(
    const __half* __restrict__ Qg, const __half* __restrict__ Kg,
    const __half* __restrict__ Vg, const float* __restrict__ mask,
    __half* __restrict__ AO)
{
    extern __shared__ __align__(16) char fsm[];
    __half* Qs = (__half*)(fsm + FQ_OFF);
    float* smask = (float*)(fsm + FM_OFF);

    const int h  = blockIdx.y;
    const int bq = blockIdx.x * 128;
    const int tid  = threadIdx.x;
    const int lane = tid & 31;
    const int warp = tid >> 5;
    const int oct = lane >> 3;
    const int oj  = lane & 7;
    const int cb  = (lane & 3) * 2;

    const u32 smemBase = (u32)__cvta_generic_to_shared(fsm);
    const u32 sQ = smemBase + FQ_OFF;
    const u32 sK = smemBase + FK_OFF;
    const u32 sV = smemBase + FV_OFF;

    #pragma unroll
    for (int l = 0; l < 4; l++)
    {
        int idx = tid + l * 256;
        int r  = idx >> 3;
        int cc = (idx & 7) * 8;
        *(int4*)(Qs + r * 72 + cc) =
            *(const int4*)(Qg + (size_t)(bq + r) * MD + h * HDIM + cc);
    }
    // whole mask once, pre-scaled into exp2 domain
    for (int i = tid; i < TTOT; i += 256) smask[i] = mask[i] * LOG2E;

    {
        #pragma unroll
        for (int l = 0; l < 2; l++)
        {
            int idx = tid + l * 256;
            int r  = idx >> 3;
            int cc = (idx & 7) * 8;
            cp16(sK + (u32)(r * 72 + cc) * 2u, Kg + (size_t)r * MD + h * HDIM + cc);
            cp16(sV + (u32)(r * 72 + cc) * 2u, Vg + (size_t)r * MD + h * HDIM + cc);
        }
        cp_commit();
    }

    __syncthreads();
    u32 qa[4][4];
    #pragma unroll
    for (int kf = 0; kf < 4; kf++)
    {
        int row = warp * 16 + (oct & 1) * 8 + oj;
        int col = kf * 16 + (oct >> 1) * 8;
        ldsm4(qa[kf], sQ + (u32)(row * 72 + col) * 2u);
    }

    float m0 = -1e30f;
    float m1 = -1e30f;
    float l0 = 0.0f;
    float l1 = 0.0f;
    float oacc[8][4];
    #pragma unroll
    for (int dt = 0; dt < 8; dt++)
    {
        #pragma unroll
        for (int x = 0; x < 4; x++) oacc[dt][x] = 0.0f;
    }

    const int NT = TTOT / 64;
    for (int t = 0; t < NT; t++)
    {
        if (t + 1 < NT)
        {
            const u32 so = (u32)((t + 1) % 3) * KV_STAGE;
            #pragma unroll
            for (int l = 0; l < 2; l++)
            {
                int idx = tid + l * 256;
                int r  = idx >> 3;
                int cc = (idx & 7) * 8;
                cp16(sK + so + (u32)(r * 72 + cc) * 2u,
                     Kg + (size_t)((t + 1) * 64 + r) * MD + h * HDIM + cc);
                cp16(sV + so + (u32)(r * 72 + cc) * 2u,
                     Vg + (size_t)((t + 1) * 64 + r) * MD + h * HDIM + cc);
            }
            cp_commit();
            cp_wait1();
        }
        else
        {
            cp_wait0();
        }
        __syncthreads();   // single barrier per iteration (3-stage ring)

        const u32 so = (u32)(t % 3) * KV_STAGE;

        float s[8][4];
        #pragma unroll
        for (int jt = 0; jt < 8; jt++)
        {
            #pragma unroll
            for (int x = 0; x < 4; x++) s[jt][x] = 0.0f;
        }
        #pragma unroll
        for (int nb = 0; nb < 4; nb++)
        {
            #pragma unroll
            for (int kf = 0; kf < 4; kf++)
            {
                u32 bfr[4];
                int row = nb * 16 + (oct >> 1) * 8 + oj;
                int col = kf * 16 + (oct & 1) * 8;
                ldsm4(bfr, sK + so + (u32)(row * 72 + col) * 2u);
                mma16816(s[2 * nb + 0], qa[kf], bfr[0], bfr[1]);
                mma16816(s[2 * nb + 1], qa[kf], bfr[2], bfr[3]);
            }
        }

        float mx0 = -1e30f;
        float mx1 = -1e30f;
        #pragma unroll
        for (int jt = 0; jt < 8; jt++)
        {
            float mk0 = smask[t * 64 + jt * 8 + cb];
            float mk1 = smask[t * 64 + jt * 8 + cb + 1];
            s[jt][0] += mk0;
            s[jt][1] += mk1;
            s[jt][2] += mk0;
            s[jt][3] += mk1;
            mx0 = fmaxf(mx0, fmaxf(s[jt][0], s[jt][1]));
            mx1 = fmaxf(mx1, fmaxf(s[jt][2], s[jt][3]));
        }
        mx0 = fmaxf(mx0, __shfl_xor_sync(0xffffffffu, mx0, 1));
        mx0 = fmaxf(mx0, __shfl_xor_sync(0xffffffffu, mx0, 2));
        mx1 = fmaxf(mx1, __shfl_xor_sync(0xffffffffu, mx1, 1));
        mx1 = fmaxf(mx1, __shfl_xor_sync(0xffffffffu, mx1, 2));
        float mn0 = fmaxf(m0, mx0);
        float a0  = exp2f(m0 - mn0);
        m0 = mn0;
        float mn1 = fmaxf(m1, mx1);
        float a1  = exp2f(m1 - mn1);
        m1 = mn1;

        float rs0 = 0.0f;
        float rs1 = 0.0f;
        #pragma unroll
        for (int jt = 0; jt < 8; jt++)
        {
            s[jt][0] = exp2f(s[jt][0] - m0); rs0 += s[jt][0];
            s[jt][1] = exp2f(s[jt][1] - m0); rs0 += s[jt][1];
            s[jt][2] = exp2f(s[jt][2] - m1); rs1 += s[jt][2];
            s[jt][3] = exp2f(s[jt][3] - m1); rs1 += s[jt][3];
        }
        l0 = l0 * a0 + rs0;
        l1 = l1 * a1 + rs1;

        u32 pa[4][4];
        #pragma unroll
        for (int kf = 0; kf < 4; kf++)
        {
            pa[kf][0] = packh2(s[2 * kf + 0][0], s[2 * kf + 0][1]);
            pa[kf][1] = packh2(s[2 * kf + 0][2], s[2 * kf + 0][3]);
            pa[kf][2] = packh2(s[2 * kf + 1][0], s[2 * kf + 1][1]);
            pa[kf][3] = packh2(s[2 * kf + 1][2], s[2 * kf + 1][3]);
        }
        #pragma unroll
        for (int dt = 0; dt < 8; dt++)
        {
            oacc[dt][0] *= a0;
            oacc[dt][1] *= a0;
            oacc[dt][2] *= a1;
            oacc[dt][3] *= a1;
        }
        #pragma unroll
        for (int db = 0; db < 4; db++)
        {
            #pragma unroll
            for (int kf = 0; kf < 4; kf++)
            {
                u32 bfr[4];
                int row = kf * 16 + (oct & 1) * 8 + oj;
                int col = db * 16 + (oct >> 1) * 8;
                ldsm4t(bfr, sV + so + (u32)(row * 72 + col) * 2u);
                mma16816(oacc[2 * db + 0], pa[kf], bfr[0], bfr[1]);
                mma16816(oacc[2 * db + 1], pa[kf], bfr[2], bfr[3]);
            }
        }
    }

    l0 += __shfl_xor_sync(0xffffffffu, l0, 1);
    l0 += __shfl_xor_sync(0xffffffffu, l0, 2);
    l1 += __shfl_xor_sync(0xffffffffu, l1, 1);
    l1 += __shfl_xor_sync(0xffffffffu, l1, 2);
    float inv0 = 1.0f / l0;
    float inv1 = 1.0f / l1;

    #pragma unroll
    for (int dt = 0; dt < 8; dt++)
    {
        int row = bq + warp * 16 + (lane >> 2);
        int col = h * HDIM + dt * 8 + cb;
        *(__half2*)(AO + (size_t)row * MD + col) =
            __floats2half2_rn(oacc[dt][0] * inv0, oacc[dt][1] * inv0);
        *(__half2*)(AO + (size_t)(row + 8) * MD + col) =
            __floats2half2_rn(oacc[dt][2] * inv1, oacc[dt][3] * inv1);
    }
}

// ----------------------------------------------------------------------------
extern "C" void kernel_launch(void* const* d_in, const int* in_sizes, int n_in,
                              void* d_out, int out_size)
{
    const float* hidden = (const float*)d_in[0];
    const float* enc    = (const float*)d_in[1];
    const float* mask   = (const float*)d_in[2];
    const float* qw  = (const float*)d_in[3];
    const float* qb  = (const float*)d_in[4];
    const float* kw  = (const float*)d_in[5];
    const float* kb  = (const float*)d_in[6];
    const float* vw  = (const float*)d_in[7];
    const float* vb  = (const float*)d_in[8];
    const float* nq  = (const float*)d_in[9];
    const float* nk  = (const float*)d_in[10];
    const float* akw = (const float*)d_in[13];
    const float* akb = (const float*)d_in[14];
    const float* avw = (const float*)d_in[15];
    const float* avb = (const float*)d_in[16];
    const float* nak = (const float*)d_in[18];
    const float* ow  = (const float*)d_in[19];
    const float* ob  = (const float*)d_in[20];
    float* outp = (float*)d_out;

    __half* h16 = 0;
    __half* e16 = 0;
    __half* w16 = 0;
    __half* Q16 = 0;
    __half* K16 = 0;
    __half* V16 = 0;
    __half* AO16 = 0;
    cudaGetSymbolAddress((void**)&h16,  g_h16);
    cudaGetSymbolAddress((void**)&e16,  g_e16);
    cudaGetSymbolAddress((void**)&w16,  g_w16);
    cudaGetSymbolAddress((void**)&Q16,  g_Q16);
    cudaGetSymbolAddress((void**)&K16,  g_K16);
    cudaGetSymbolAddress((void**)&V16,  g_V16);
    cudaGetSymbolAddress((void**)&AO16, g_AO16);

    __half* wq16  = w16 + 0 * (size_t)MD * MD;
    __half* wk16  = w16 + 1 * (size_t)MD * MD;
    __half* wv16  = w16 + 2 * (size_t)MD * MD;
    __half* wak16 = w16 + 3 * (size_t)MD * MD;
    __half* wav16 = w16 + 4 * (size_t)MD * MD;
    __half* wo16  = w16 + 5 * (size_t)MD * MD;

    const int nw4 = MD * MD / 4;
    const int nh4 = SHID * MD / 4;
    const int ne4 = SENC * MD / 4;

    CvtJobs jobs;
    jobs.src[0] = hidden;  jobs.dst[0] = h16;   jobs.n4[0] = nh4;
    jobs.src[1] = enc;     jobs.dst[1] = e16;   jobs.n4[1] = ne4;
    jobs.src[2] = qw;      jobs.dst[2] = wq16;  jobs.n4[2] = nw4;
    jobs.src[3] = kw;      jobs.dst[3] = wk16;  jobs.n4[3] = nw4;
    jobs.src[4] = vw;      jobs.dst[4] = wv16;  jobs.n4[4] = nw4;
    jobs.src[5] = akw;     jobs.dst[5] = wak16; jobs.n4[5] = nw4;
    jobs.src[6] = avw;     jobs.dst[6] = wav16; jobs.n4[6] = nw4;
    jobs.src[7] = ow;      jobs.dst[7] = wo16;  jobs.n4[7] = nw4;

    int maxB = (nh4 / 4 + 255) / 256;
    dim3 cgrid(maxB, 8, 1);
    dim3 cblk(256, 1, 1);
    cvt_multi<<<cgrid, cblk>>>(jobs);

    cudaFuncSetAttribute(gemm_f16x, cudaFuncAttributeMaxDynamicSharedMemorySize, G_SMEM);
    cudaFuncSetAttribute(flash16, cudaFuncAttributeMaxDynamicSharedMemorySize, F_SMEM);

    dim3 blk128(128, 1, 1);

    // one launch: all 5 projections (Q,K,V hidden + K,V encoder),
    // RMSNorm fused into Q and K epilogues.
    // Q also gets log2(e)/sqrt(64) for the exp2-domain softmax.
    GemmJobs jP;
    jP.A[0] = h16;  jP.W[0] = wq16;  jP.bias[0] = qb;  jP.normw[0] = nq;
    jP.C[0] = Q16;  jP.M[0] = SHID;  jP.mode[0] = 2;   jP.scale[0] = 0.125f * LOG2E;
    jP.A[1] = h16;  jP.W[1] = wk16;  jP.bias[1] = kb;  jP.normw[1] = nk;
    jP.C[1] = K16;  jP.M[1] = SHID;  jP.mode[1] = 2;   jP.scale[1] = 1.0f;
    jP.A[2] = h16;  jP.W[2] = wv16;  jP.bias[2] = vb;  jP.normw[2] = nq;
    jP.C[2] = V16;  jP.M[2] = SHID;  jP.mode[2] = 1;   jP.scale[2] = 1.0f;
    jP.A[3] = e16;  jP.W[3] = wak16; jP.bias[3] = akb; jP.normw[3] = nak;
    jP.C[3] = K16 + (size_t)SHID * MD;  jP.M[3] = SENC;  jP.mode[3] = 2;  jP.scale[3] = 1.0f;
    jP.A[4] = e16;  jP.W[4] = wav16; jP.bias[4] = avb; jP.normw[4] = nq;
    jP.C[4] = V16 + (size_t)SHID * MD;  jP.M[4] = SENC;  jP.mode[4] = 1;  jP.scale[4] = 1.0f;
    dim3 gP(MD / 128, SHID / 128, 5);
    gemm_f16x<<<gP, blk128, G_SMEM>>>(jP, MD, MD);

    // flash attention
    dim3 gF(SHID / 128, NHEAD, 1);
    dim3 fblk(256, 1, 1);
    flash16<<<gF, fblk, F_SMEM>>>(Q16, K16, V16, mask, AO16);

    // output projection -> fp32 d_out
    GemmJobs jO;
    jO.A[0] = AO16;  jO.W[0] = wo16;  jO.bias[0] = ob;  jO.normw[0] = nq;
    jO.C[0] = outp;  jO.M[0] = SHID;  jO.mode[0] = 0;   jO.scale[0] = 1.0f;
    #pragma unroll
    for (int i = 1; i < 5; i++)
    {
        jO.A[i] = AO16;  jO.W[i] = wo16;  jO.bias[i] = ob;  jO.normw[i] = nq;
        jO.C[i] = outp;  jO.M[i] = 0;     jO.mode[i] = 0;   jO.scale[i] = 1.0f;
    }
    dim3 gO(MD / 128, SHID / 128, 1);
    gemm_f16x<<<gO, blk128, G_SMEM>>>(jO, MD, MD);
}

// round 15
// speedup vs baseline: 1.8005x; 1.0351x over previous
#include <cuda_runtime.h>
#include <cuda_fp16.h>
#include <stdint.h>
#include <math.h>

typedef unsigned int u32;

#define MD    1536
#define SHID  2048
#define SENC  256
#define TTOT  2304
#define NHEAD 24
#define HDIM  64

#define LOG2E 1.44269504088896340736f
// Fixed softmax shift (exp2 domain). RMSNorm bounds |q.k|*scale*log2e <= 11.6,
// so exp2(s - 12) never overflows and max p ~ 0.75.
#define M_FIX 12.0f

// ---------------- scratch (__device__ globals: allocation-free rule) --------
__device__ __half g_h16 [SHID * MD];
__device__ __half g_e16 [SENC * MD];
__device__ __half g_w16 [6 * MD * MD];
__device__ __half g_Q16 [SHID * MD];
__device__ __half g_K16 [TTOT * MD];
__device__ __half g_V16 [TTOT * MD];
__device__ __half g_AO16[SHID * MD];

// ---------------- warp-mma helpers ------------------------------------------
__device__ __forceinline__ void ldsm4(u32* r, u32 addr)
{
    asm volatile("ldmatrix.sync.aligned.m8n8.x4.shared.b16 {%0,%1,%2,%3}, [%4];"
                 : "=r"(r[0]), "=r"(r[1]), "=r"(r[2]), "=r"(r[3]) : "r"(addr));
}

__device__ __forceinline__ void ldsm4t(u32* r, u32 addr)
{
    asm volatile("ldmatrix.sync.aligned.m8n8.x4.trans.shared.b16 {%0,%1,%2,%3}, [%4];"
                 : "=r"(r[0]), "=r"(r[1]), "=r"(r[2]), "=r"(r[3]) : "r"(addr));
}

__device__ __forceinline__ void mma16816(float* c, const u32* a, u32 b0, u32 b1)
{
    asm volatile(
        "mma.sync.aligned.m16n8k16.row.col.f32.f16.f16.f32 "
        "{%0,%1,%2,%3}, {%4,%5,%6,%7}, {%8,%9}, {%0,%1,%2,%3};"
        : "+f"(c[0]), "+f"(c[1]), "+f"(c[2]), "+f"(c[3])
        : "r"(a[0]), "r"(a[1]), "r"(a[2]), "r"(a[3]), "r"(b0), "r"(b1));
}

__device__ __forceinline__ u32 packh2(float x, float y)
{
    __half2 h = __floats2half2_rn(x, y);
    return *reinterpret_cast<u32*>(&h);
}

__device__ __forceinline__ void cp16(u32 smem_dst, const void* gmem_src)
{
    asm volatile("cp.async.cg.shared.global [%0], [%1], 16;"
                 :: "r"(smem_dst), "l"(gmem_src));
}

__device__ __forceinline__ void cp_commit()
{
    asm volatile("cp.async.commit_group;");
}

__device__ __forceinline__ void cp_wait1()
{
    asm volatile("cp.async.wait_group 1;");
}

__device__ __forceinline__ void cp_wait0()
{
    asm volatile("cp.async.wait_group 0;");
}

// ---------------- merged fp32 -> fp16 convert (one launch, 8 segments) -----
struct CvtJobs
{
    const float* src[8];
    __half*      dst[8];
    int          n4[8];
};

__global__ __launch_bounds__(256) void cvt_multi(CvtJobs jobs)
{
    int seg = blockIdx.y;
    const float* __restrict__ src = jobs.src[seg];
    __half* __restrict__ dst = jobs.dst[seg];
    int n4 = jobs.n4[seg];
    int i0 = (blockIdx.x * 256 + threadIdx.x) * 4;
    if (i0 >= n4) return;
    #pragma unroll
    for (int j = 0; j < 4; j++)
    {
        int i = i0 + j;
        float4 v = ((const float4*)src)[i];
        ((__half2*)dst)[2 * i + 0] = __floats2half2_rn(v.x, v.y);
        ((__half2*)dst)[2 * i + 1] = __floats2half2_rn(v.z, v.w);
    }
}

// ---------------- multi-job fp16 GEMM, 64x64 warp tiles, BK=32 --------------
// (R10 configuration — best measured; do not touch)
struct GemmJobs
{
    const __half* A[5];
    const __half* W[5];
    const float*  bias[5];
    const float*  normw[5];
    void*         C[5];
    int           M[5];
    int           mode[5];
    float         scale[5];
};

#define GSTG_B   10240            // one stage of one matrix: 128*40 halves
#define GB_OFF   30720            // 3 stages of A
#define G_SMEM   61440

__global__ __launch_bounds__(128) void gemm_f16x(GemmJobs job, int N, int K)
{
    extern __shared__ __align__(16) char gsm[];
    const int z = blockIdx.z;
    const int bm = blockIdx.y * 128;
    if (bm >= job.M[z]) return;
    const __half* __restrict__ A = job.A[z];
    const __half* __restrict__ W = job.W[z];
    const float* __restrict__ bias = job.bias[z];
    const float* __restrict__ normw = job.normw[z];
    void* Cout = job.C[z];
    const int mode = job.mode[z];
    const float nscale = job.scale[z];

    const int bn = blockIdx.x * 128;
    const int tid  = threadIdx.x;
    const int lane = tid & 31;
    const int warp = tid >> 5;
    const int wm  = warp & 1;
    const int wn  = warp >> 1;
    const int oct = lane >> 3;
    const int oj  = lane & 7;

    const u32 sA = (u32)__cvta_generic_to_shared(gsm);
    const u32 sB = sA + GB_OFF;

    float acc[4][8][4];
    #pragma unroll
    for (int mi = 0; mi < 4; mi++)
        #pragma unroll
        for (int ni = 0; ni < 8; ni++)
            #pragma unroll
            for (int x = 0; x < 4; x++) acc[mi][ni][x] = 0.0f;

    const int KT = K >> 5;

    #pragma unroll
    for (int pt = 0; pt < 2; pt++)
    {
        const u32 so = (u32)pt * GSTG_B;
        #pragma unroll
        for (int l = 0; l < 4; l++)
        {
            int idx = tid + l * 128;
            int row = idx >> 2;
            int ch  = idx & 3;
            u32 d = so + (u32)(row * 40 + ch * 8) * 2u;
            cp16(sA + d, A + (size_t)(bm + row) * K + pt * 32 + ch * 8);
            cp16(sB + d, W + (size_t)(bn + row) * K + pt * 32 + ch * 8);
        }
        cp_commit();
    }

    for (int kt = 0; kt < KT; kt++)
    {
        if (kt == KT - 1) cp_wait0(); else cp_wait1();
        __syncthreads();

        if (kt + 2 < KT)
        {
            const int nt = kt + 2;
            const u32 so = (u32)(nt % 3) * GSTG_B;
            #pragma unroll
            for (int l = 0; l < 4; l++)
            {
                int idx = tid + l * 128;
                int row = idx >> 2;
                int ch  = idx & 3;
                u32 d = so + (u32)(row * 40 + ch * 8) * 2u;
                cp16(sA + d, A + (size_t)(bm + row) * K + nt * 32 + ch * 8);
                cp16(sB + d, W + (size_t)(bn + row) * K + nt * 32 + ch * 8);
            }
            cp_commit();
        }

        const u32 so = (u32)(kt % 3) * GSTG_B;
        #pragma unroll
        for (int ks = 0; ks < 2; ks++)
        {
            const int ksh = ks * 16;
            u32 af[4][4];
            #pragma unroll
            for (int mi = 0; mi < 4; mi++)
            {
                int row = wm * 64 + mi * 16 + (oct & 1) * 8 + oj;
                int col = ksh + (oct >> 1) * 8;
                ldsm4(af[mi], sA + so + (u32)(row * 40 + col) * 2u);
            }
            u32 bf[4][4];
            #pragma unroll
            for (int nb = 0; nb < 4; nb++)
            {
                int row = wn * 64 + nb * 16 + (oct >> 1) * 8 + oj;
                int col = ksh + (oct & 1) * 8;
                ldsm4(bf[nb], sB + so + (u32)(row * 40 + col) * 2u);
            }
            #pragma unroll
            for (int mi = 0; mi < 4; mi++)
            {
                #pragma unroll
                for (int nb = 0; nb < 4; nb++)
                {
                    mma16816(acc[mi][2 * nb + 0], af[mi], bf[nb][0], bf[nb][1]);
                    mma16816(acc[mi][2 * nb + 1], af[mi], bf[nb][2], bf[nb][3]);
                }
            }
        }
    }

    #pragma unroll
    for (int ni = 0; ni < 8; ni++)
    {
        int col = bn + wn * 64 + ni * 8 + (lane & 3) * 2;
        float b0 = bias[col];
        float b1 = bias[col + 1];
        #pragma unroll
        for (int mi = 0; mi < 4; mi++)
        {
            acc[mi][ni][0] += b0;
            acc[mi][ni][1] += b1;
            acc[mi][ni][2] += b0;
            acc[mi][ni][3] += b1;
        }
    }

    if (mode == 2)
    {
        __half* C = (__half*)Cout;
        #pragma unroll
        for (int mi = 0; mi < 4; mi++)
        {
            float s0 = 0.0f;
            float s1 = 0.0f;
            #pragma unroll
            for (int ni = 0; ni < 8; ni++)
            {
                s0 += acc[mi][ni][0] * acc[mi][ni][0] + acc[mi][ni][1] * acc[mi][ni][1];
                s1 += acc[mi][ni][2] * acc[mi][ni][2] + acc[mi][ni][3] * acc[mi][ni][3];
            }
            s0 += __shfl_xor_sync(0xffffffffu, s0, 1);
            s0 += __shfl_xor_sync(0xffffffffu, s0, 2);
            s1 += __shfl_xor_sync(0xffffffffu, s1, 1);
            s1 += __shfl_xor_sync(0xffffffffu, s1, 2);
            float rs0 = rsqrtf(s0 * (1.0f / HDIM) + 1e-6f) * nscale;
            float rs1 = rsqrtf(s1 * (1.0f / HDIM) + 1e-6f) * nscale;
            int row = bm + wm * 64 + mi * 16 + (lane >> 2);
            #pragma unroll
            for (int ni = 0; ni < 8; ni++)
            {
                int wcol = ni * 8 + (lane & 3) * 2;
                float w0 = normw[wcol];
                float w1 = normw[wcol + 1];
                int col = bn + wn * 64 + wcol;
                *(__half2*)(C + (size_t)row * N + col) =
                    __floats2half2_rn(acc[mi][ni][0] * rs0 * w0, acc[mi][ni][1] * rs0 * w1);
                *(__half2*)(C + (size_t)(row + 8) * N + col) =
                    __floats2half2_rn(acc[mi][ni][2] * rs1 * w0, acc[mi][ni][3] * rs1 * w1);
            }
        }
    }
    else if (mode == 1)
    {
        __half* C = (__half*)Cout;
        #pragma unroll
        for (int mi = 0; mi < 4; mi++)
        {
            int row = bm + wm * 64 + mi * 16 + (lane >> 2);
            #pragma unroll
            for (int ni = 0; ni < 8; ni++)
            {
                int col = bn + wn * 64 + ni * 8 + (lane & 3) * 2;
                *(__half2*)(C + (size_t)row * N + col) =
                    __floats2half2_rn(acc[mi][ni][0], acc[mi][ni][1]);
                *(__half2*)(C + (size_t)(row + 8) * N + col) =
                    __floats2half2_rn(acc[mi][ni][2], acc[mi][ni][3]);
            }
        }
    }
    else
    {
        float* C = (float*)Cout;
        #pragma unroll
        for (int mi = 0; mi < 4; mi++)
        {
            int row = bm + wm * 64 + mi * 16 + (lane >> 2);
            #pragma unroll
            for (int ni = 0; ni < 8; ni++)
            {
                int col = bn + wn * 64 + ni * 8 + (lane & 3) * 2;
                *(float2*)(C + (size_t)row * N + col) =
                    make_float2(acc[mi][ni][0], acc[mi][ni][1]);
                *(float2*)(C + (size_t)(row + 8) * N + col) =
                    make_float2(acc[mi][ni][2], acc[mi][ni][3]);
            }
        }
    }
}

// ---------------- fp16 flash attention (fixed-shift exp2 softmax) -----------
// 256 threads = 8 warps; q-tile 128 (16 rows/warp), kv-tile 64, d=64.
// Q pre-scaled by log2(e)/sqrt(HDIM); smask = mask*log2(e) - M_FIX.
// No online max: p = exp2(s + smask); softmax shift-invariance makes the
// result identical, and the RMSNorm bound guarantees no overflow.
#define FQ_OFF   0
#define FK_OFF   18432
#define FV_OFF   46080
#define FM_OFF   73728
#define F_SMEM   82944
#define KV_STAGE 9216

__global__ __launch_bounds__(256) void flash16(
    const __half* __restrict__ Qg, const __half* __restrict__ Kg,
    const __half* __restrict__ Vg, const float* __restrict__ mask,
    __half* __restrict__ AO)
{
    extern __shared__ __align__(16) char fsm[];
    __half* Qs = (__half*)(fsm + FQ_OFF);
    float* smask = (float*)(fsm + FM_OFF);

    const int h  = blockIdx.y;
    const int bq = blockIdx.x * 128;
    const int tid  = threadIdx.x;
    const int lane = tid & 31;
    const int warp = tid >> 5;
    const int oct = lane >> 3;
    const int oj  = lane & 7;
    const int cb  = (lane & 3) * 2;

    const u32 smemBase = (u32)__cvta_generic_to_shared(fsm);
    const u32 sQ = smemBase + FQ_OFF;
    const u32 sK = smemBase + FK_OFF;
    const u32 sV = smemBase + FV_OFF;

    #pragma unroll
    for (int l = 0; l < 4; l++)
    {
        int idx = tid + l * 256;
        int r  = idx >> 3;
        int cc = (idx & 7) * 8;
        *(int4*)(Qs + r * 72 + cc) =
            *(const int4*)(Qg + (size_t)(bq + r) * MD + h * HDIM + cc);
    }
    // mask once, folded into exp2 domain with the fixed shift
    for (int i = tid; i < TTOT; i += 256) smask[i] = mask[i] * LOG2E - M_FIX;

    {
        #pragma unroll
        for (int l = 0; l < 2; l++)
        {
            int idx = tid + l * 256;
            int r  = idx >> 3;
            int cc = (idx & 7) * 8;
            cp16(sK + (u32)(r * 72 + cc) * 2u, Kg + (size_t)r * MD + h * HDIM + cc);
            cp16(sV + (u32)(r * 72 + cc) * 2u, Vg + (size_t)r * MD + h * HDIM + cc);
        }
        cp_commit();
    }

    __syncthreads();
    u32 qa[4][4];
    #pragma unroll
    for (int kf = 0; kf < 4; kf++)
    {
        int row = warp * 16 + (oct & 1) * 8 + oj;
        int col = kf * 16 + (oct >> 1) * 8;
        ldsm4(qa[kf], sQ + (u32)(row * 72 + col) * 2u);
    }

    float l0 = 0.0f;
    float l1 = 0.0f;
    float oacc[8][4];
    #pragma unroll
    for (int dt = 0; dt < 8; dt++)
    {
        #pragma unroll
        for (int x = 0; x < 4; x++) oacc[dt][x] = 0.0f;
    }

    const int NT = TTOT / 64;
    for (int t = 0; t < NT; t++)
    {
        if (t + 1 < NT)
        {
            const u32 so = (u32)((t + 1) % 3) * KV_STAGE;
            #pragma unroll
            for (int l = 0; l < 2; l++)
            {
                int idx = tid + l * 256;
                int r  = idx >> 3;
                int cc = (idx & 7) * 8;
                cp16(sK + so + (u32)(r * 72 + cc) * 2u,
                     Kg + (size_t)((t + 1) * 64 + r) * MD + h * HDIM + cc);
                cp16(sV + so + (u32)(r * 72 + cc) * 2u,
                     Vg + (size_t)((t + 1) * 64 + r) * MD + h * HDIM + cc);
            }
            cp_commit();
            cp_wait1();
        }
        else
        {
            cp_wait0();
        }
        __syncthreads();   // single barrier per iteration (3-stage ring)

        const u32 so = (u32)(t % 3) * KV_STAGE;

        float s[8][4];
        #pragma unroll
        for (int jt = 0; jt < 8; jt++)
        {
            #pragma unroll
            for (int x = 0; x < 4; x++) s[jt][x] = 0.0f;
        }
        #pragma unroll
        for (int nb = 0; nb < 4; nb++)
        {
            #pragma unroll
            for (int kf = 0; kf < 4; kf++)
            {
                u32 bfr[4];
                int row = nb * 16 + (oct >> 1) * 8 + oj;
                int col = kf * 16 + (oct & 1) * 8;
                ldsm4(bfr, sK + so + (u32)(row * 72 + col) * 2u);
                mma16816(s[2 * nb + 0], qa[kf], bfr[0], bfr[1]);
                mma16816(s[2 * nb + 1], qa[kf], bfr[2], bfr[3]);
            }
        }

        // fixed-shift exp2 softmax numerator + row-sum partials
        float rs0 = 0.0f;
        float rs1 = 0.0f;
        #pragma unroll
        for (int jt = 0; jt < 8; jt++)
        {
            float mk0 = smask[t * 64 + jt * 8 + cb];
            float mk1 = smask[t * 64 + jt * 8 + cb + 1];
            s[jt][0] = exp2f(s[jt][0] + mk0); rs0 += s[jt][0];
            s[jt][1] = exp2f(s[jt][1] + mk1); rs0 += s[jt][1];
            s[jt][2] = exp2f(s[jt][2] + mk0); rs1 += s[jt][2];
            s[jt][3] = exp2f(s[jt][3] + mk1); rs1 += s[jt][3];
        }
        l0 += rs0;
        l1 += rs1;

        u32 pa[4][4];
        #pragma unroll
        for (int kf = 0; kf < 4; kf++)
        {
            pa[kf][0] = packh2(s[2 * kf + 0][0], s[2 * kf + 0][1]);
            pa[kf][1] = packh2(s[2 * kf + 0][2], s[2 * kf + 0][3]);
            pa[kf][2] = packh2(s[2 * kf + 1][0], s[2 * kf + 1][1]);
            pa[kf][3] = packh2(s[2 * kf + 1][2], s[2 * kf + 1][3]);
        }
        #pragma unroll
        for (int db = 0; db < 4; db++)
        {
            #pragma unroll
            for (int kf = 0; kf < 4; kf++)
            {
                u32 bfr[4];
                int row = kf * 16 + (oct & 1) * 8 + oj;
                int col = db * 16 + (oct >> 1) * 8;
                ldsm4t(bfr, sV + so + (u32)(row * 72 + col) * 2u);
                mma16816(oacc[2 * db + 0], pa[kf], bfr[0], bfr[1]);
                mma16816(oacc[2 * db + 1], pa[kf], bfr[2], bfr[3]);
            }
        }
    }

    l0 += __shfl_xor_sync(0xffffffffu, l0, 1);
    l0 += __shfl_xor_sync(0xffffffffu, l0, 2);
    l1 += __shfl_xor_sync(0xffffffffu, l1, 1);
    l1 += __shfl_xor_sync(0xffffffffu, l1, 2);
    float inv0 = 1.0f / l0;
    float inv1 = 1.0f / l1;

    #pragma unroll
    for (int dt = 0; dt < 8; dt++)
    {
        int row = bq + warp * 16 + (lane >> 2);
        int col = h * HDIM + dt * 8 + cb;
        *(__half2*)(AO + (size_t)row * MD + col) =
            __floats2half2_rn(oacc[dt][0] * inv0, oacc[dt][1] * inv0);
        *(__half2*)(AO + (size_t)(row + 8) * MD + col) =
            __floats2half2_rn(oacc[dt][2] * inv1, oacc[dt][3] * inv1);
    }
}

// ----------------------------------------------------------------------------
extern "C" void kernel_launch(void* const* d_in, const int* in_sizes, int n_in,
                              void* d_out, int out_size)
{
    const float* hidden = (const float*)d_in[0];
    const float* enc    = (const float*)d_in[1];
    const float* mask   = (const float*)d_in[2];
    const float* qw  = (const float*)d_in[3];
    const float* qb  = (const float*)d_in[4];
    const float* kw  = (const float*)d_in[5];
    const float* kb  = (const float*)d_in[6];
    const float* vw  = (const float*)d_in[7];
    const float* vb  = (const float*)d_in[8];
    const float* nq  = (const float*)d_in[9];
    const float* nk  = (const float*)d_in[10];
    const float* akw = (const float*)d_in[13];
    const float* akb = (const float*)d_in[14];
    const float* avw = (const float*)d_in[15];
    const float* avb = (const float*)d_in[16];
    const float* nak = (const float*)d_in[18];
    const float* ow  = (const float*)d_in[19];
    const float* ob  = (const float*)d_in[20];
    float* outp = (float*)d_out;

    __half* h16 = 0;
    __half* e16 = 0;
    __half* w16 = 0;
    __half* Q16 = 0;
    __half* K16 = 0;
    __half* V16 = 0;
    __half* AO16 = 0;
    cudaGetSymbolAddress((void**)&h16,  g_h16);
    cudaGetSymbolAddress((void**)&e16,  g_e16);
    cudaGetSymbolAddress((void**)&w16,  g_w16);
    cudaGetSymbolAddress((void**)&Q16,  g_Q16);
    cudaGetSymbolAddress((void**)&K16,  g_K16);
    cudaGetSymbolAddress((void**)&V16,  g_V16);
    cudaGetSymbolAddress((void**)&AO16, g_AO16);

    __half* wq16  = w16 + 0 * (size_t)MD * MD;
    __half* wk16  = w16 + 1 * (size_t)MD * MD;
    __half* wv16  = w16 + 2 * (size_t)MD * MD;
    __half* wak16 = w16 + 3 * (size_t)MD * MD;
    __half* wav16 = w16 + 4 * (size_t)MD * MD;
    __half* wo16  = w16 + 5 * (size_t)MD * MD;

    const int nw4 = MD * MD / 4;
    const int nh4 = SHID * MD / 4;
    const int ne4 = SENC * MD / 4;

    CvtJobs jobs;
    jobs.src[0] = hidden;  jobs.dst[0] = h16;   jobs.n4[0] = nh4;
    jobs.src[1] = enc;     jobs.dst[1] = e16;   jobs.n4[1] = ne4;
    jobs.src[2] = qw;      jobs.dst[2] = wq16;  jobs.n4[2] = nw4;
    jobs.src[3] = kw;      jobs.dst[3] = wk16;  jobs.n4[3] = nw4;
    jobs.src[4] = vw;      jobs.dst[4] = wv16;  jobs.n4[4] = nw4;
    jobs.src[5] = akw;     jobs.dst[5] = wak16; jobs.n4[5] = nw4;
    jobs.src[6] = avw;     jobs.dst[6] = wav16; jobs.n4[6] = nw4;
    jobs.src[7] = ow;      jobs.dst[7] = wo16;  jobs.n4[7] = nw4;

    int maxB = (nh4 / 4 + 255) / 256;
    dim3 cgrid(maxB, 8, 1);
    dim3 cblk(256, 1, 1);
    cvt_multi<<<cgrid, cblk>>>(jobs);

    cudaFuncSetAttribute(gemm_f16x, cudaFuncAttributeMaxDynamicSharedMemorySize, G_SMEM);
    cudaFuncSetAttribute(flash16, cudaFuncAttributeMaxDynamicSharedMemorySize, F_SMEM);

    dim3 blk128(128, 1, 1);

    // one launch: all 5 projections; RMSNorm fused into Q and K epilogues.
    // Q also gets log2(e)/sqrt(64) for the exp2-domain softmax.
    GemmJobs jP;
    jP.A[0] = h16;  jP.W[0] = wq16;  jP.bias[0] = qb;  jP.normw[0] = nq;
    jP.C[0] = Q16;  jP.M[0] = SHID;  jP.mode[0] = 2;   jP.scale[0] = 0.125f * LOG2E;
    jP.A[1] = h16;  jP.W[1] = wk16;  jP.bias[1] = kb;  jP.normw[1] = nk;
    jP.C[1] = K16;  jP.M[1] = SHID;  jP.mode[1] = 2;   jP.scale[1] = 1.0f;
    jP.A[2] = h16;  jP.W[2] = wv16;  jP.bias[2] = vb;  jP.normw[2] = nq;
    jP.C[2] = V16;  jP.M[2] = SHID;  jP.mode[2] = 1;   jP.scale[2] = 1.0f;
    jP.A[3] = e16;  jP.W[3] = wak16; jP.bias[3] = akb; jP.normw[3] = nak;
    jP.C[3] = K16 + (size_t)SHID * MD;  jP.M[3] = SENC;  jP.mode[3] = 2;  jP.scale[3] = 1.0f;
    jP.A[4] = e16;  jP.W[4] = wav16; jP.bias[4] = avb; jP.normw[4] = nq;
    jP.C[4] = V16 + (size_t)SHID * MD;  jP.M[4] = SENC;  jP.mode[4] = 1;  jP.scale[4] = 1.0f;
    dim3 gP(MD / 128, SHID / 128, 5);
    gemm_f16x<<<gP, blk128, G_SMEM>>>(jP, MD, MD);

    // flash attention
    dim3 gF(SHID / 128, NHEAD, 1);
    dim3 fblk(256, 1, 1);
    flash16<<<gF, fblk, F_SMEM>>>(Q16, K16, V16, mask, AO16);

    // output projection -> fp32 d_out
    GemmJobs jO;
    jO.A[0] = AO16;  jO.W[0] = wo16;  jO.bias[0] = ob;  jO.normw[0] = nq;
    jO.C[0] = outp;  jO.M[0] = SHID;  jO.mode[0] = 0;   jO.scale[0] = 1.0f;
    #pragma unroll
    for (int i = 1; i < 5; i++)
    {
        jO.A[i] = AO16;  jO.W[i] = wo16;  jO.bias[i] = ob;  jO.normw[i] = nq;
        jO.C[i] = outp;  jO.M[i] = 0;     jO.mode[i] = 0;   jO.scale[i] = 1.0f;
    }
    dim3 gO(MD / 128, SHID / 128, 1);
    gemm_f16x<<<gO, blk128, G_SMEM>>>(jO, MD, MD);
}

// round 16
// speedup vs baseline: 1.8284x; 1.0155x over previous
#include <cuda_runtime.h>
#include <cuda_fp16.h>
#include <stdint.h>
#include <math.h>

typedef unsigned int u32;

#define MD    1536
#define SHID  2048
#define SENC  256
#define TTOT  2304
#define NHEAD 24
#define HDIM  64

#define LOG2E 1.44269504088896340736f
// Fixed softmax shift (exp2 domain). RMSNorm bounds |q.k|*scale*log2e <= 11.6,
// so exp2(s - 12) never overflows and max p ~ 0.75.
#define M_FIX 12.0f

// ---------------- scratch (__device__ globals: allocation-free rule) --------
__device__ __half g_h16 [SHID * MD];
__device__ __half g_e16 [SENC * MD];
__device__ __half g_w16 [6 * MD * MD];
__device__ __half g_Q16 [SHID * MD];
__device__ __half g_K16 [TTOT * MD];
__device__ __half g_V16 [TTOT * MD];
__device__ __half g_AO16[SHID * MD];

// ---------------- warp-mma helpers ------------------------------------------
__device__ __forceinline__ void ldsm4(u32* r, u32 addr)
{
    asm volatile("ldmatrix.sync.aligned.m8n8.x4.shared.b16 {%0,%1,%2,%3}, [%4];"
                 : "=r"(r[0]), "=r"(r[1]), "=r"(r[2]), "=r"(r[3]) : "r"(addr));
}

__device__ __forceinline__ void ldsm4t(u32* r, u32 addr)
{
    asm volatile("ldmatrix.sync.aligned.m8n8.x4.trans.shared.b16 {%0,%1,%2,%3}, [%4];"
                 : "=r"(r[0]), "=r"(r[1]), "=r"(r[2]), "=r"(r[3]) : "r"(addr));
}

__device__ __forceinline__ void mma16816(float* c, const u32* a, u32 b0, u32 b1)
{
    asm volatile(
        "mma.sync.aligned.m16n8k16.row.col.f32.f16.f16.f32 "
        "{%0,%1,%2,%3}, {%4,%5,%6,%7}, {%8,%9}, {%0,%1,%2,%3};"
        : "+f"(c[0]), "+f"(c[1]), "+f"(c[2]), "+f"(c[3])
        : "r"(a[0]), "r"(a[1]), "r"(a[2]), "r"(a[3]), "r"(b0), "r"(b1));
}

__device__ __forceinline__ u32 packh2(float x, float y)
{
    __half2 h = __floats2half2_rn(x, y);
    return *reinterpret_cast<u32*>(&h);
}

__device__ __forceinline__ void cp16(u32 smem_dst, const void* gmem_src)
{
    asm volatile("cp.async.cg.shared.global [%0], [%1], 16;"
                 :: "r"(smem_dst), "l"(gmem_src));
}

__device__ __forceinline__ void cp_commit()
{
    asm volatile("cp.async.commit_group;");
}

__device__ __forceinline__ void cp_wait1()
{
    asm volatile("cp.async.wait_group 1;");
}

__device__ __forceinline__ void cp_wait0()
{
    asm volatile("cp.async.wait_group 0;");
}

// ---------------- merged fp32 -> fp16 convert (one launch, 8 segments) -----
struct CvtJobs
{
    const float* src[8];
    __half*      dst[8];
    int          n4[8];
};

__global__ __launch_bounds__(256) void cvt_multi(CvtJobs jobs)
{
    int seg = blockIdx.y;
    const float* __restrict__ src = jobs.src[seg];
    __half* __restrict__ dst = jobs.dst[seg];
    int n4 = jobs.n4[seg];
    int i0 = (blockIdx.x * 256 + threadIdx.x) * 4;
    if (i0 >= n4) return;
    #pragma unroll
    for (int j = 0; j < 4; j++)
    {
        int i = i0 + j;
        float4 v = ((const float4*)src)[i];
        ((__half2*)dst)[2 * i + 0] = __floats2half2_rn(v.x, v.y);
        ((__half2*)dst)[2 * i + 1] = __floats2half2_rn(v.z, v.w);
    }
}

// ---------------- multi-job fp16 GEMM, 64x64 warp tiles, BK=32 --------------
// (R10 configuration — best measured; do not touch)
struct GemmJobs
{
    const __half* A[5];
    const __half* W[5];
    const float*  bias[5];
    const float*  normw[5];
    void*         C[5];
    int           M[5];
    int           mode[5];
    float         scale[5];
};

#define GSTG_B   10240            // one stage of one matrix: 128*40 halves
#define GB_OFF   30720            // 3 stages of A
#define G_SMEM   61440

__global__ __launch_bounds__(128) void gemm_f16x(GemmJobs job, int N, int K)
{
    extern __shared__ __align__(16) char gsm[];
    const int z = blockIdx.z;
    const int bm = blockIdx.y * 128;
    if (bm >= job.M[z]) return;
    const __half* __restrict__ A = job.A[z];
    const __half* __restrict__ W = job.W[z];
    const float* __restrict__ bias = job.bias[z];
    const float* __restrict__ normw = job.normw[z];
    void* Cout = job.C[z];
    const int mode = job.mode[z];
    const float nscale = job.scale[z];

    const int bn = blockIdx.x * 128;
    const int tid  = threadIdx.x;
    const int lane = tid & 31;
    const int warp = tid >> 5;
    const int wm  = warp & 1;
    const int wn  = warp >> 1;
    const int oct = lane >> 3;
    const int oj  = lane & 7;

    const u32 sA = (u32)__cvta_generic_to_shared(gsm);
    const u32 sB = sA + GB_OFF;

    float acc[4][8][4];
    #pragma unroll
    for (int mi = 0; mi < 4; mi++)
        #pragma unroll
        for (int ni = 0; ni < 8; ni++)
            #pragma unroll
            for (int x = 0; x < 4; x++) acc[mi][ni][x] = 0.0f;

    const int KT = K >> 5;

    #pragma unroll
    for (int pt = 0; pt < 2; pt++)
    {
        const u32 so = (u32)pt * GSTG_B;
        #pragma unroll
        for (int l = 0; l < 4; l++)
        {
            int idx = tid + l * 128;
            int row = idx >> 2;
            int ch  = idx & 3;
            u32 d = so + (u32)(row * 40 + ch * 8) * 2u;
            cp16(sA + d, A + (size_t)(bm + row) * K + pt * 32 + ch * 8);
            cp16(sB + d, W + (size_t)(bn + row) * K + pt * 32 + ch * 8);
        }
        cp_commit();
    }

    for (int kt = 0; kt < KT; kt++)
    {
        if (kt == KT - 1) cp_wait0(); else cp_wait1();
        __syncthreads();

        if (kt + 2 < KT)
        {
            const int nt = kt + 2;
            const u32 so = (u32)(nt % 3) * GSTG_B;
            #pragma unroll
            for (int l = 0; l < 4; l++)
            {
                int idx = tid + l * 128;
                int row = idx >> 2;
                int ch  = idx & 3;
                u32 d = so + (u32)(row * 40 + ch * 8) * 2u;
                cp16(sA + d, A + (size_t)(bm + row) * K + nt * 32 + ch * 8);
                cp16(sB + d, W + (size_t)(bn + row) * K + nt * 32 + ch * 8);
            }
            cp_commit();
        }

        const u32 so = (u32)(kt % 3) * GSTG_B;
        #pragma unroll
        for (int ks = 0; ks < 2; ks++)
        {
            const int ksh = ks * 16;
            u32 af[4][4];
            #pragma unroll
            for (int mi = 0; mi < 4; mi++)
            {
                int row = wm * 64 + mi * 16 + (oct & 1) * 8 + oj;
                int col = ksh + (oct >> 1) * 8;
                ldsm4(af[mi], sA + so + (u32)(row * 40 + col) * 2u);
            }
            u32 bf[4][4];
            #pragma unroll
            for (int nb = 0; nb < 4; nb++)
            {
                int row = wn * 64 + nb * 16 + (oct >> 1) * 8 + oj;
                int col = ksh + (oct & 1) * 8;
                ldsm4(bf[nb], sB + so + (u32)(row * 40 + col) * 2u);
            }
            #pragma unroll
            for (int mi = 0; mi < 4; mi++)
            {
                #pragma unroll
                for (int nb = 0; nb < 4; nb++)
                {
                    mma16816(acc[mi][2 * nb + 0], af[mi], bf[nb][0], bf[nb][1]);
                    mma16816(acc[mi][2 * nb + 1], af[mi], bf[nb][2], bf[nb][3]);
                }
            }
        }
    }

    #pragma unroll
    for (int ni = 0; ni < 8; ni++)
    {
        int col = bn + wn * 64 + ni * 8 + (lane & 3) * 2;
        float b0 = bias[col];
        float b1 = bias[col + 1];
        #pragma unroll
        for (int mi = 0; mi < 4; mi++)
        {
            acc[mi][ni][0] += b0;
            acc[mi][ni][1] += b1;
            acc[mi][ni][2] += b0;
            acc[mi][ni][3] += b1;
        }
    }

    if (mode == 2)
    {
        __half* C = (__half*)Cout;
        #pragma unroll
        for (int mi = 0; mi < 4; mi++)
        {
            float s0 = 0.0f;
            float s1 = 0.0f;
            #pragma unroll
            for (int ni = 0; ni < 8; ni++)
            {
                s0 += acc[mi][ni][0] * acc[mi][ni][0] + acc[mi][ni][1] * acc[mi][ni][1];
                s1 += acc[mi][ni][2] * acc[mi][ni][2] + acc[mi][ni][3] * acc[mi][ni][3];
            }
            s0 += __shfl_xor_sync(0xffffffffu, s0, 1);
            s0 += __shfl_xor_sync(0xffffffffu, s0, 2);
            s1 += __shfl_xor_sync(0xffffffffu, s1, 1);
            s1 += __shfl_xor_sync(0xffffffffu, s1, 2);
            float rs0 = rsqrtf(s0 * (1.0f / HDIM) + 1e-6f) * nscale;
            float rs1 = rsqrtf(s1 * (1.0f / HDIM) + 1e-6f) * nscale;
            int row = bm + wm * 64 + mi * 16 + (lane >> 2);
            #pragma unroll
            for (int ni = 0; ni < 8; ni++)
            {
                int wcol = ni * 8 + (lane & 3) * 2;
                float w0 = normw[wcol];
                float w1 = normw[wcol + 1];
                int col = bn + wn * 64 + wcol;
                *(__half2*)(C + (size_t)row * N + col) =
                    __floats2half2_rn(acc[mi][ni][0] * rs0 * w0, acc[mi][ni][1] * rs0 * w1);
                *(__half2*)(C + (size_t)(row + 8) * N + col) =
                    __floats2half2_rn(acc[mi][ni][2] * rs1 * w0, acc[mi][ni][3] * rs1 * w1);
            }
        }
    }
    else if (mode == 1)
    {
        __half* C = (__half*)Cout;
        #pragma unroll
        for (int mi = 0; mi < 4; mi++)
        {
            int row = bm + wm * 64 + mi * 16 + (lane >> 2);
            #pragma unroll
            for (int ni = 0; ni < 8; ni++)
            {
                int col = bn + wn * 64 + ni * 8 + (lane & 3) * 2;
                *(__half2*)(C + (size_t)row * N + col) =
                    __floats2half2_rn(acc[mi][ni][0], acc[mi][ni][1]);
                *(__half2*)(C + (size_t)(row + 8) * N + col) =
                    __floats2half2_rn(acc[mi][ni][2], acc[mi][ni][3]);
            }
        }
    }
    else
    {
        float* C = (float*)Cout;
        #pragma unroll
        for (int mi = 0; mi < 4; mi++)
        {
            int row = bm + wm * 64 + mi * 16 + (lane >> 2);
            #pragma unroll
            for (int ni = 0; ni < 8; ni++)
            {
                int col = bn + wn * 64 + ni * 8 + (lane & 3) * 2;
                *(float2*)(C + (size_t)row * N + col) =
                    make_float2(acc[mi][ni][0], acc[mi][ni][1]);
                *(float2*)(C + (size_t)(row + 8) * N + col) =
                    make_float2(acc[mi][ni][2], acc[mi][ni][3]);
            }
        }
    }
}

// ---------------- fp16 flash attention (fat warps: 32 q-rows/warp) ----------
// 128 threads = 4 warps; q-tile 128 (32 rows/warp = 2 m-frags), kv-tile 64.
// Per warp per kv-tile: 32 ldsm feed 128 mma (2x the old density).
// Fixed-shift exp2 softmax (smask = mask*log2e - M_FIX).
#define FQ_OFF   0
#define FK_OFF   18432
#define FV_OFF   46080
#define FM_OFF   73728
#define F_SMEM   82944
#define KV_STAGE 9216

__global__ __launch_bounds__(128, 2) void flash16(
    const __half* __restrict__ Qg, const __half* __restrict__ Kg,
    const __half* __restrict__ Vg, const float* __restrict__ mask,
    __half* __restrict__ AO)
{
    extern __shared__ __align__(16) char fsm[];
    __half* Qs = (__half*)(fsm + FQ_OFF);
    float* smask = (float*)(fsm + FM_OFF);

    const int h  = blockIdx.y;
    const int bq = blockIdx.x * 128;
    const int tid  = threadIdx.x;
    const int lane = tid & 31;
    const int warp = tid >> 5;      // 0..3, each owns 32 q rows
    const int oct = lane >> 3;
    const int oj  = lane & 7;
    const int cb  = (lane & 3) * 2;

    const u32 smemBase = (u32)__cvta_generic_to_shared(fsm);
    const u32 sQ = smemBase + FQ_OFF;
    const u32 sK = smemBase + FK_OFF;
    const u32 sV = smemBase + FV_OFF;

    // load Q tile: 128 rows x 64 halves, 8 int4 per thread
    #pragma unroll
    for (int l = 0; l < 8; l++)
    {
        int idx = tid + l * 128;
        int r  = idx >> 3;
        int cc = (idx & 7) * 8;
        *(int4*)(Qs + r * 72 + cc) =
            *(const int4*)(Qg + (size_t)(bq + r) * MD + h * HDIM + cc);
    }
    // mask once, folded into exp2 domain with the fixed shift
    for (int i = tid; i < TTOT; i += 128) smask[i] = mask[i] * LOG2E - M_FIX;

    // preload kv tile 0 (stage 0): 512 chunks per matrix, 4 per thread
    {
        #pragma unroll
        for (int l = 0; l < 4; l++)
        {
            int idx = tid + l * 128;
            int r  = idx >> 3;
            int cc = (idx & 7) * 8;
            cp16(sK + (u32)(r * 72 + cc) * 2u, Kg + (size_t)r * MD + h * HDIM + cc);
            cp16(sV + (u32)(r * 72 + cc) * 2u, Vg + (size_t)r * MD + h * HDIM + cc);
        }
        cp_commit();
    }

    __syncthreads();
    u32 qa[2][4][4];
    #pragma unroll
    for (int m = 0; m < 2; m++)
    {
        #pragma unroll
        for (int kf = 0; kf < 4; kf++)
        {
            int row = warp * 32 + m * 16 + (oct & 1) * 8 + oj;
            int col = kf * 16 + (oct >> 1) * 8;
            ldsm4(qa[m][kf], sQ + (u32)(row * 72 + col) * 2u);
        }
    }

    float lacc[2][2];
    lacc[0][0] = 0.0f; lacc[0][1] = 0.0f;
    lacc[1][0] = 0.0f; lacc[1][1] = 0.0f;
    float oacc[2][8][4];
    #pragma unroll
    for (int m = 0; m < 2; m++)
        #pragma unroll
        for (int dt = 0; dt < 8; dt++)
            #pragma unroll
            for (int x = 0; x < 4; x++) oacc[m][dt][x] = 0.0f;

    const int NT = TTOT / 64;
    for (int t = 0; t < NT; t++)
    {
        if (t + 1 < NT)
        {
            const u32 so = (u32)((t + 1) % 3) * KV_STAGE;
            #pragma unroll
            for (int l = 0; l < 4; l++)
            {
                int idx = tid + l * 128;
                int r  = idx >> 3;
                int cc = (idx & 7) * 8;
                cp16(sK + so + (u32)(r * 72 + cc) * 2u,
                     Kg + (size_t)((t + 1) * 64 + r) * MD + h * HDIM + cc);
                cp16(sV + so + (u32)(r * 72 + cc) * 2u,
                     Vg + (size_t)((t + 1) * 64 + r) * MD + h * HDIM + cc);
            }
            cp_commit();
            cp_wait1();
        }
        else
        {
            cp_wait0();
        }
        __syncthreads();   // single barrier per iteration (3-stage ring)

        const u32 so = (u32)(t % 3) * KV_STAGE;

        // S = Q @ K^T : 16 ldsm feed 64 mma
        float s[2][8][4];
        #pragma unroll
        for (int m = 0; m < 2; m++)
            #pragma unroll
            for (int jt = 0; jt < 8; jt++)
                #pragma unroll
                for (int x = 0; x < 4; x++) s[m][jt][x] = 0.0f;
        #pragma unroll
        for (int nb = 0; nb < 4; nb++)
        {
            #pragma unroll
            for (int kf = 0; kf < 4; kf++)
            {
                u32 bfr[4];
                int row = nb * 16 + (oct >> 1) * 8 + oj;
                int col = kf * 16 + (oct & 1) * 8;
                ldsm4(bfr, sK + so + (u32)(row * 72 + col) * 2u);
                #pragma unroll
                for (int m = 0; m < 2; m++)
                {
                    mma16816(s[m][2 * nb + 0], qa[m][kf], bfr[0], bfr[1]);
                    mma16816(s[m][2 * nb + 1], qa[m][kf], bfr[2], bfr[3]);
                }
            }
        }

        // fixed-shift exp2 softmax numerator + row-sum partials
        #pragma unroll
        for (int m = 0; m < 2; m++)
        {
            float rs0 = 0.0f;
            float rs1 = 0.0f;
            #pragma unroll
            for (int jt = 0; jt < 8; jt++)
            {
                float mk0 = smask[t * 64 + jt * 8 + cb];
                float mk1 = smask[t * 64 + jt * 8 + cb + 1];
                s[m][jt][0] = exp2f(s[m][jt][0] + mk0); rs0 += s[m][jt][0];
                s[m][jt][1] = exp2f(s[m][jt][1] + mk1); rs0 += s[m][jt][1];
                s[m][jt][2] = exp2f(s[m][jt][2] + mk0); rs1 += s[m][jt][2];
                s[m][jt][3] = exp2f(s[m][jt][3] + mk1); rs1 += s[m][jt][3];
            }
            lacc[m][0] += rs0;
            lacc[m][1] += rs1;
        }

        u32 pa[2][4][4];
        #pragma unroll
        for (int m = 0; m < 2; m++)
        {
            #pragma unroll
            for (int kf = 0; kf < 4; kf++)
            {
                pa[m][kf][0] = packh2(s[m][2 * kf + 0][0], s[m][2 * kf + 0][1]);
                pa[m][kf][1] = packh2(s[m][2 * kf + 0][2], s[m][2 * kf + 0][3]);
                pa[m][kf][2] = packh2(s[m][2 * kf + 1][0], s[m][2 * kf + 1][1]);
                pa[m][kf][3] = packh2(s[m][2 * kf + 1][2], s[m][2 * kf + 1][3]);
            }
        }
        // O += P @ V : 16 ldsm.trans feed 64 mma
        #pragma unroll
        for (int db = 0; db < 4; db++)
        {
            #pragma unroll
            for (int kf = 0; kf < 4; kf++)
            {
                u32 bfr[4];
                int row = kf * 16 + (oct & 1) * 8 + oj;
                int col = db * 16 + (oct >> 1) * 8;
                ldsm4t(bfr, sV + so + (u32)(row * 72 + col) * 2u);
                #pragma unroll
                for (int m = 0; m < 2; m++)
                {
                    mma16816(oacc[m][2 * db + 0], pa[m][kf], bfr[0], bfr[1]);
                    mma16816(oacc[m][2 * db + 1], pa[m][kf], bfr[2], bfr[3]);
                }
            }
        }
    }

    #pragma unroll
    for (int m = 0; m < 2; m++)
    {
        float l0 = lacc[m][0];
        float l1 = lacc[m][1];
        l0 += __shfl_xor_sync(0xffffffffu, l0, 1);
        l0 += __shfl_xor_sync(0xffffffffu, l0, 2);
        l1 += __shfl_xor_sync(0xffffffffu, l1, 1);
        l1 += __shfl_xor_sync(0xffffffffu, l1, 2);
        float inv0 = 1.0f / l0;
        float inv1 = 1.0f / l1;

        #pragma unroll
        for (int dt = 0; dt < 8; dt++)
        {
            int row = bq + warp * 32 + m * 16 + (lane >> 2);
            int col = h * HDIM + dt * 8 + cb;
            *(__half2*)(AO + (size_t)row * MD + col) =
                __floats2half2_rn(oacc[m][dt][0] * inv0, oacc[m][dt][1] * inv0);
            *(__half2*)(AO + (size_t)(row + 8) * MD + col) =
                __floats2half2_rn(oacc[m][dt][2] * inv1, oacc[m][dt][3] * inv1);
        }
    }
}

// ----------------------------------------------------------------------------
extern "C" void kernel_launch(void* const* d_in, const int* in_sizes, int n_in,
                              void* d_out, int out_size)
{
    const float* hidden = (const float*)d_in[0];
    const float* enc    = (const float*)d_in[1];
    const float* mask   = (const float*)d_in[2];
    const float* qw  = (const float*)d_in[3];
    const float* qb  = (const float*)d_in[4];
    const float* kw  = (const float*)d_in[5];
    const float* kb  = (const float*)d_in[6];
    const float* vw  = (const float*)d_in[7];
    const float* vb  = (const float*)d_in[8];
    const float* nq  = (const float*)d_in[9];
    const float* nk  = (const float*)d_in[10];
    const float* akw = (const float*)d_in[13];
    const float* akb = (const float*)d_in[14];
    const float* avw = (const float*)d_in[15];
    const float* avb = (const float*)d_in[16];
    const float* nak = (const float*)d_in[18];
    const float* ow  = (const float*)d_in[19];
    const float* ob  = (const float*)d_in[20];
    float* outp = (float*)d_out;

    __half* h16 = 0;
    __half* e16 = 0;
    __half* w16 = 0;
    __half* Q16 = 0;
    __half* K16 = 0;
    __half* V16 = 0;
    __half* AO16 = 0;
    cudaGetSymbolAddress((void**)&h16,  g_h16);
    cudaGetSymbolAddress((void**)&e16,  g_e16);
    cudaGetSymbolAddress((void**)&w16,  g_w16);
    cudaGetSymbolAddress((void**)&Q16,  g_Q16);
    cudaGetSymbolAddress((void**)&K16,  g_K16);
    cudaGetSymbolAddress((void**)&V16,  g_V16);
    cudaGetSymbolAddress((void**)&AO16, g_AO16);

    __half* wq16  = w16 + 0 * (size_t)MD * MD;
    __half* wk16  = w16 + 1 * (size_t)MD * MD;
    __half* wv16  = w16 + 2 * (size_t)MD * MD;
    __half* wak16 = w16 + 3 * (size_t)MD * MD;
    __half* wav16 = w16 + 4 * (size_t)MD * MD;
    __half* wo16  = w16 + 5 * (size_t)MD * MD;

    const int nw4 = MD * MD / 4;
    const int nh4 = SHID * MD / 4;
    const int ne4 = SENC * MD / 4;

    CvtJobs jobs;
    jobs.src[0] = hidden;  jobs.dst[0] = h16;   jobs.n4[0] = nh4;
    jobs.src[1] = enc;     jobs.dst[1] = e16;   jobs.n4[1] = ne4;
    jobs.src[2] = qw;      jobs.dst[2] = wq16;  jobs.n4[2] = nw4;
    jobs.src[3] = kw;      jobs.dst[3] = wk16;  jobs.n4[3] = nw4;
    jobs.src[4] = vw;      jobs.dst[4] = wv16;  jobs.n4[4] = nw4;
    jobs.src[5] = akw;     jobs.dst[5] = wak16; jobs.n4[5] = nw4;
    jobs.src[6] = avw;     jobs.dst[6] = wav16; jobs.n4[6] = nw4;
    jobs.src[7] = ow;      jobs.dst[7] = wo16;  jobs.n4[7] = nw4;

    int maxB = (nh4 / 4 + 255) / 256;
    dim3 cgrid(maxB, 8, 1);
    dim3 cblk(256, 1, 1);
    cvt_multi<<<cgrid, cblk>>>(jobs);

    cudaFuncSetAttribute(gemm_f16x, cudaFuncAttributeMaxDynamicSharedMemorySize, G_SMEM);
    cudaFuncSetAttribute(flash16, cudaFuncAttributeMaxDynamicSharedMemorySize, F_SMEM);

    dim3 blk128(128, 1, 1);

    // one launch: all 5 projections; RMSNorm fused into Q and K epilogues.
    // Q also gets log2(e)/sqrt(64) for the exp2-domain softmax.
    GemmJobs jP;
    jP.A[0] = h16;  jP.W[0] = wq16;  jP.bias[0] = qb;  jP.normw[0] = nq;
    jP.C[0] = Q16;  jP.M[0] = SHID;  jP.mode[0] = 2;   jP.scale[0] = 0.125f * LOG2E;
    jP.A[1] = h16;  jP.W[1] = wk16;  jP.bias[1] = kb;  jP.normw[1] = nk;
    jP.C[1] = K16;  jP.M[1] = SHID;  jP.mode[1] = 2;   jP.scale[1] = 1.0f;
    jP.A[2] = h16;  jP.W[2] = wv16;  jP.bias[2] = vb;  jP.normw[2] = nq;
    jP.C[2] = V16;  jP.M[2] = SHID;  jP.mode[2] = 1;   jP.scale[2] = 1.0f;
    jP.A[3] = e16;  jP.W[3] = wak16; jP.bias[3] = akb; jP.normw[3] = nak;
    jP.C[3] = K16 + (size_t)SHID * MD;  jP.M[3] = SENC;  jP.mode[3] = 2;  jP.scale[3] = 1.0f;
    jP.A[4] = e16;  jP.W[4] = wav16; jP.bias[4] = avb; jP.normw[4] = nq;
    jP.C[4] = V16 + (size_t)SHID * MD;  jP.M[4] = SENC;  jP.mode[4] = 1;  jP.scale[4] = 1.0f;
    dim3 gP(MD / 128, SHID / 128, 5);
    gemm_f16x<<<gP, blk128, G_SMEM>>>(jP, MD, MD);

    // flash attention (fat warps)
    dim3 gF(SHID / 128, NHEAD, 1);
    flash16<<<gF, blk128, F_SMEM>>>(Q16, K16, V16, mask, AO16);

    // output projection -> fp32 d_out
    GemmJobs jO;
    jO.A[0] = AO16;  jO.W[0] = wo16;  jO.bias[0] = ob;  jO.normw[0] = nq;
    jO.C[0] = outp;  jO.M[0] = SHID;  jO.mode[0] = 0;   jO.scale[0] = 1.0f;
    #pragma unroll
    for (int i = 1; i < 5; i++)
    {
        jO.A[i] = AO16;  jO.W[i] = wo16;  jO.bias[i] = ob;  jO.normw[i] = nq;
        jO.C[i] = outp;  jO.M[i] = 0;     jO.mode[i] = 0;   jO.scale[i] = 1.0f;
    }
    dim3 gO(MD / 128, SHID / 128, 1);
    gemm_f16x<<<gO, blk128, G_SMEM>>>(jO, MD, MD);
}